// round 5
// baseline (speedup 1.0000x reference)
#include <cuda_runtime.h>
#include <cuda_bf16.h>
#include <math.h>
#include <stdint.h>

#define B_ 8
#define P_ 100
#define N_ 50000
#define D_ 128
#define K_ 512
#define CAP 4096
#define SAMPN 2048

// Scratch (static device globals — no runtime allocation)
__device__ float g_fastsim[(size_t)B_ * P_ * N_];          // fallback-only
__device__ float g_sample[(size_t)B_ * P_ * SAMPN];        // 6.4 MB
__device__ unsigned g_lo[B_ * P_];
__device__ int g_cnt[B_ * P_];
__device__ unsigned long long g_cand[(size_t)B_ * P_ * CAP];  // 26 MB

__device__ __forceinline__ unsigned fkey(float f) {
    unsigned u = __float_as_uint(f);
    return (u & 0x80000000u) ? ~u : (u | 0x80000000u);   // monotonic increasing
}

// ---------------------------------------------------------------------------
// GEMM: fast_sim tile = pos @ neg^T, bf16x2-split on mma.sync (HMMA).
// CTA: 128(m) x 128(n), K=128. 8 warps, 64x32 each.
// MODE 0: dense store to g_sample (stride SAMPN). MODE 1: threshold-append.
// ---------------------------------------------------------------------------
#define TNB 128
#define TSTR 136
#define TILE_BYTES (128 * TSTR * 2)
#define SMEM_TC_BYTES (4 * TILE_BYTES)

__device__ __forceinline__ uint32_t smem_u32(const void* p) {
    return (uint32_t)__cvta_generic_to_shared(p);
}
__device__ __forceinline__ void ldm_x4(uint32_t& r0, uint32_t& r1, uint32_t& r2, uint32_t& r3,
                                       uint32_t addr) {
    asm volatile("ldmatrix.sync.aligned.m8n8.x4.shared.b16 {%0,%1,%2,%3}, [%4];"
                 : "=r"(r0), "=r"(r1), "=r"(r2), "=r"(r3) : "r"(addr));
}
__device__ __forceinline__ void ldm_x2(uint32_t& r0, uint32_t& r1, uint32_t addr) {
    asm volatile("ldmatrix.sync.aligned.m8n8.x2.shared.b16 {%0,%1}, [%2];"
                 : "=r"(r0), "=r"(r1) : "r"(addr));
}
__device__ __forceinline__ void mma16816(float& c0, float& c1, float& c2, float& c3,
                                         uint32_t a0, uint32_t a1, uint32_t a2, uint32_t a3,
                                         uint32_t b0, uint32_t b1) {
    asm volatile("mma.sync.aligned.m16n8k16.row.col.f32.bf16.bf16.f32 "
                 "{%0,%1,%2,%3}, {%4,%5,%6,%7}, {%8,%9}, {%0,%1,%2,%3};"
                 : "+f"(c0), "+f"(c1), "+f"(c2), "+f"(c3)
                 : "r"(a0), "r"(a1), "r"(a2), "r"(a3), "r"(b0), "r"(b1));
}

__device__ __forceinline__ void try_append(int row, int n, float v, unsigned lo) {
    unsigned k = fkey(v);
    if (k >= lo) {
        int pos = atomicAdd(&g_cnt[row], 1);
        if (pos < CAP)
            g_cand[(size_t)row * CAP + pos] = ((unsigned long long)k << 32) | (unsigned)n;
    }
}

template <int MODE>
__global__ void __launch_bounds__(256, 1) gemm_kernel(const float* __restrict__ pos,
                                                      const float* __restrict__ neg) {
    extern __shared__ __nv_bfloat16 smem[];
    __nv_bfloat16* Ah = smem;
    __nv_bfloat16* Al = smem + 128 * TSTR;
    __nv_bfloat16* Bh = smem + 2 * 128 * TSTR;
    __nv_bfloat16* Bl = smem + 3 * 128 * TSTR;

    int tid = threadIdx.x;
    int lane = tid & 31;
    int wid = tid >> 5;
    int b = blockIdx.y;
    int n0 = blockIdx.x * TNB;

    const float* Ab = pos + (size_t)b * P_ * D_;
    const float* Bb = neg + (size_t)b * N_ * D_;

    // ---- load + convert A (pad rows zero) and B (pad n zero)
#pragma unroll
    for (int i = 0; i < 16; ++i) {
        int f = i * 256 + tid;
        int r = f >> 5;
        int c = (f & 31) << 2;

        float4 va = make_float4(0.f, 0.f, 0.f, 0.f);
        if (r < P_) va = *(const float4*)(Ab + (size_t)r * D_ + c);
        __nv_bfloat162 h0 = __float22bfloat162_rn(make_float2(va.x, va.y));
        __nv_bfloat162 h1 = __float22bfloat162_rn(make_float2(va.z, va.w));
        float2 hf0 = __bfloat1622float2(h0), hf1 = __bfloat1622float2(h1);
        __nv_bfloat162 l0 = __float22bfloat162_rn(make_float2(va.x - hf0.x, va.y - hf0.y));
        __nv_bfloat162 l1 = __float22bfloat162_rn(make_float2(va.z - hf1.x, va.w - hf1.y));
        *(uint2*)(Ah + r * TSTR + c) = make_uint2(*(uint32_t*)&h0, *(uint32_t*)&h1);
        *(uint2*)(Al + r * TSTR + c) = make_uint2(*(uint32_t*)&l0, *(uint32_t*)&l1);

        int n = n0 + r;
        float4 vb = make_float4(0.f, 0.f, 0.f, 0.f);
        if (n < N_) vb = *(const float4*)(Bb + (size_t)n * D_ + c);
        h0 = __float22bfloat162_rn(make_float2(vb.x, vb.y));
        h1 = __float22bfloat162_rn(make_float2(vb.z, vb.w));
        hf0 = __bfloat1622float2(h0); hf1 = __bfloat1622float2(h1);
        l0 = __float22bfloat162_rn(make_float2(vb.x - hf0.x, vb.y - hf0.y));
        l1 = __float22bfloat162_rn(make_float2(vb.z - hf1.x, vb.w - hf1.y));
        *(uint2*)(Bh + r * TSTR + c) = make_uint2(*(uint32_t*)&h0, *(uint32_t*)&h1);
        *(uint2*)(Bl + r * TSTR + c) = make_uint2(*(uint32_t*)&l0, *(uint32_t*)&l1);
    }
    __syncthreads();

    int wm = wid >> 2;
    int wn = wid & 3;
    int mbase = wm * 64;
    int nbase = wn * 32;

    float c[4][4][4];
#pragma unroll
    for (int i = 0; i < 4; ++i)
#pragma unroll
        for (int j = 0; j < 4; ++j)
#pragma unroll
            for (int q = 0; q < 4; ++q) c[i][j][q] = 0.f;

    const __nv_bfloat16* pA[3] = {Ah, Ah, Al};
    const __nv_bfloat16* pB[3] = {Bh, Bl, Bh};

#pragma unroll
    for (int pr = 0; pr < 3; ++pr) {
        uint32_t abase = smem_u32(pA[pr]);
        uint32_t bbase = smem_u32(pB[pr]);
        uint32_t aoff = abase + (uint32_t)(lane & 15) * (TSTR * 2) + (uint32_t)(lane >> 4) * 16;
        uint32_t boff = bbase + (uint32_t)(lane & 7) * (TSTR * 2) + (uint32_t)((lane >> 3) & 1) * 16;

#pragma unroll
        for (int kc = 0; kc < 8; ++kc) {
            uint32_t kb = kc * 32;
            uint32_t a0[4], a1[4], a2[4], a3[4];
#pragma unroll
            for (int i = 0; i < 4; ++i)
                ldm_x4(a0[i], a1[i], a2[i], a3[i],
                       aoff + (uint32_t)(mbase + i * 16) * (TSTR * 2) + kb);
            uint32_t b0[4], b1[4];
#pragma unroll
            for (int j = 0; j < 4; ++j)
                ldm_x2(b0[j], b1[j],
                       boff + (uint32_t)(nbase + j * 8) * (TSTR * 2) + kb);
#pragma unroll
            for (int i = 0; i < 4; ++i)
#pragma unroll
                for (int j = 0; j < 4; ++j)
                    mma16816(c[i][j][0], c[i][j][1], c[i][j][2], c[i][j][3],
                             a0[i], a1[i], a2[i], a3[i], b0[j], b1[j]);
        }
    }

    // ---- epilogue
    int mrow0 = mbase + (lane >> 2);
    int ncol0 = n0 + nbase + (lane & 3) * 2;

    if (MODE == 0) {
        // dense store into g_sample (row stride SAMPN); n always < SAMPN here
#pragma unroll
        for (int i = 0; i < 4; ++i) {
            int m0 = mrow0 + i * 16;
            int m1 = m0 + 8;
#pragma unroll
            for (int j = 0; j < 4; ++j) {
                int nc = ncol0 + j * 8;
                if (m0 < P_)
                    *(float2*)(g_sample + (size_t)(b * P_ + m0) * SAMPN + nc) =
                        make_float2(c[i][j][0], c[i][j][1]);
                if (m1 < P_)
                    *(float2*)(g_sample + (size_t)(b * P_ + m1) * SAMPN + nc) =
                        make_float2(c[i][j][2], c[i][j][3]);
            }
        }
    } else {
        __syncthreads();
        unsigned* lo_s = (unsigned*)smem;   // smem reuse after compute
        if (tid < 128) lo_s[tid] = (tid < P_) ? g_lo[b * P_ + tid] : 0xFFFFFFFFu;
        __syncthreads();
#pragma unroll
        for (int i = 0; i < 4; ++i) {
            int m0 = mrow0 + i * 16;
            int m1 = m0 + 8;
#pragma unroll
            for (int j = 0; j < 4; ++j) {
                int nc = ncol0 + j * 8;
                if (m0 < P_) {
                    int row = b * P_ + m0;
                    unsigned lo = lo_s[m0];
                    if (nc < N_)     try_append(row, nc,     c[i][j][0], lo);
                    if (nc + 1 < N_) try_append(row, nc + 1, c[i][j][1], lo);
                }
                if (m1 < P_) {
                    int row = b * P_ + m1;
                    unsigned lo = lo_s[m1];
                    if (nc < N_)     try_append(row, nc,     c[i][j][2], lo);
                    if (nc + 1 < N_) try_append(row, nc + 1, c[i][j][3], lo);
                }
            }
        }
    }
}

// ---------------------------------------------------------------------------
// shared radix helper
// ---------------------------------------------------------------------------
__device__ void scan_bins(unsigned* hist, unsigned* csum, int nbins, int kr,
                          int sh, unsigned prefix,
                          unsigned* s_thresh, int* s_kr, int tid) {
    int chunks = nbins >> 3;
    if (tid < chunks) {
        unsigned s = 0;
#pragma unroll
        for (int i = 0; i < 8; ++i) s += hist[tid * 8 + i];
        csum[tid] = s;
    }
    __syncthreads();
    if (tid == 0) {
        unsigned cum = 0;
        int c = chunks - 1;
        for (; c > 0; --c) {
            if (cum + csum[c] >= (unsigned)kr) break;
            cum += csum[c];
        }
        int bin = c * 8 + 7;
        for (; bin > c * 8; --bin) {
            if (cum + hist[bin] >= (unsigned)kr) break;
            cum += hist[bin];
        }
        *s_thresh = prefix | ((unsigned)bin << sh);
        *s_kr = kr - (int)cum;
    }
    __syncthreads();
}

// ---------------------------------------------------------------------------
// Threshold kernel: lo[row] = exact 64th-largest key of sample row; zero cnt.
// ---------------------------------------------------------------------------
__global__ void __launch_bounds__(256) thresh_kernel() {
    int row = blockIdx.x;
    int tid = threadIdx.x;
    const float* sim = g_sample + (size_t)row * SAMPN;

    __shared__ unsigned hist[2048];
    __shared__ unsigned csum[256];
    __shared__ unsigned s_thresh;
    __shared__ int s_kr;

    unsigned skey[8];
#pragma unroll
    for (int q = 0; q < 2; ++q) {
        float4 v = *(const float4*)(sim + tid * 8 + q * 4);
        skey[q * 4 + 0] = fkey(v.x); skey[q * 4 + 1] = fkey(v.y);
        skey[q * 4 + 2] = fkey(v.z); skey[q * 4 + 3] = fkey(v.w);
    }
    const int      shifts[3] = {21, 10, 0};
    const unsigned masks[3]  = {0x7FFu, 0x7FFu, 0x3FFu};
    const int      nbinsv[3] = {2048, 2048, 1024};
    unsigned prefix = 0, pmask = 0;
    int kr = 64;
    for (int pass = 0; pass < 3; ++pass) {
        int sh = shifts[pass]; unsigned mk = masks[pass];
#pragma unroll
        for (int i = 0; i < 8; ++i) hist[tid * 8 + i] = 0;
        __syncthreads();
#pragma unroll
        for (int i = 0; i < 8; ++i) {
            unsigned u = skey[i];
            if ((u & pmask) == prefix) atomicAdd(&hist[(u >> sh) & mk], 1u);
        }
        __syncthreads();
        scan_bins(hist, csum, nbinsv[pass], kr, sh, prefix, &s_thresh, &s_kr, tid);
        prefix = s_thresh; kr = s_kr; pmask |= mk << sh;
        __syncthreads();
    }
    if (tid == 0) {
        g_lo[row] = prefix;
        g_cnt[row] = 0;
    }
}

// ---------------------------------------------------------------------------
// Select kernel: candidates -> exact top-512 -> rescore -> softmax-agg.
// ---------------------------------------------------------------------------
#define SEL_SMEM ((2048 + 256 + CAP + CAP + K_ + K_ + K_ + 128 + 128 + 256) * 4)

__global__ void __launch_bounds__(256) select_kernel(const float* __restrict__ pos,
                                                     const float* __restrict__ neg,
                                                     const float* __restrict__ Wm,
                                                     const float* __restrict__ biasp,
                                                     const float* __restrict__ scalep,
                                                     float* __restrict__ out) {
    int row = blockIdx.x;
    int b = row / P_;
    int tid = threadIdx.x;

    extern __shared__ unsigned dsm[];
    unsigned* hist  = dsm;                 // 2048
    unsigned* csum  = hist + 2048;         // 256
    unsigned* candk = csum + 256;          // CAP
    int*      candi = (int*)(candk + CAP); // CAP
    int*      sel   = candi + CAP;         // K_
    float*    sscore = (float*)(sel + K_); // K_
    int*      ties  = (int*)(sscore + K_); // K_
    float*    ppos  = (float*)(ties + K_); // 128
    float*    spw   = ppos + 128;          // 128
    float*    red   = spw + 128;           // 256

    __shared__ unsigned s_thresh;
    __shared__ int s_kr, s_cntgt, s_cnteq;

    // ---- pos row + posW
    if (tid < D_) ppos[tid] = pos[(size_t)row * D_ + tid];
    __syncthreads();
    if (tid < D_) {
        float acc = 0.f;
#pragma unroll 8
        for (int d = 0; d < D_; ++d)
            acc = fmaf(ppos[d], Wm[d * D_ + tid], acc);
        spw[tid] = acc;
    }

    int cnt = g_cnt[row];
    bool fb = (cnt < K_) || (cnt > CAP);

    if (!fb) {
        for (int i = tid; i < cnt; i += 256) {
            unsigned long long v = g_cand[(size_t)row * CAP + i];
            candk[i] = (unsigned)(v >> 32);
            candi[i] = (int)(unsigned)v;
        }
    } else {
        // fallback: recompute full row fp32 into g_fastsim
        __syncthreads();   // ppos ready
        float* simw = g_fastsim + (size_t)row * N_;
        for (int n = tid; n < N_; n += 256) {
            const float* v = neg + ((size_t)b * N_ + n) * D_;
            float s = 0.f;
#pragma unroll 8
            for (int d = 0; d < D_; ++d) s = fmaf(ppos[d], v[d], s);
            simw[n] = s;
        }
    }
    __syncthreads();

    const int      shifts[3] = {21, 10, 0};
    const unsigned masks[3]  = {0x7FFu, 0x7FFu, 0x3FFu};
    const int      nbinsv[3] = {2048, 2048, 1024};

    // ---- exact 512th-largest key -> uth
    unsigned prefix = 0, pmask = 0;
    int kr = K_;
    const float* simr = g_fastsim + (size_t)row * N_;
    for (int pass = 0; pass < 3; ++pass) {
        int sh = shifts[pass]; unsigned mk = masks[pass];
#pragma unroll
        for (int i = 0; i < 8; ++i) hist[tid * 8 + i] = 0;
        __syncthreads();
        if (!fb) {
            for (int i = tid; i < cnt; i += 256) {
                unsigned u = candk[i];
                if ((u & pmask) == prefix) atomicAdd(&hist[(u >> sh) & mk], 1u);
            }
        } else {
            for (int n = tid; n < N_; n += 256) {
                unsigned u = fkey(simr[n]);
                if ((u & pmask) == prefix) atomicAdd(&hist[(u >> sh) & mk], 1u);
            }
        }
        __syncthreads();
        scan_bins(hist, csum, nbinsv[pass], kr, sh, prefix, &s_thresh, &s_kr, tid);
        prefix = s_thresh; kr = s_kr; pmask |= mk << sh;
        __syncthreads();
    }
    unsigned uth = prefix;

    // ---- collect winners (> uth) and ties (== uth)
    if (tid == 0) { s_cntgt = 0; s_cnteq = 0; }
    __syncthreads();
    if (!fb) {
        for (int i = tid; i < cnt; i += 256) {
            unsigned u = candk[i];
            if (u > uth) {
                int q = atomicAdd(&s_cntgt, 1);
                sel[q] = candi[i];
            } else if (u == uth) {
                int q = atomicAdd(&s_cnteq, 1);
                if (q < K_) ties[q] = candi[i];
            }
        }
    } else {
        for (int n = tid; n < N_; n += 256) {
            unsigned u = fkey(simr[n]);
            if (u > uth) {
                int q = atomicAdd(&s_cntgt, 1);
                sel[q] = n;
            } else if (u == uth) {
                int q = atomicAdd(&s_cnteq, 1);
                if (q < K_) ties[q] = n;
            }
        }
    }
    __syncthreads();
    if (tid == 0) {
        int have = s_cntgt;
        int need = K_ - have;
        int te = min(s_cnteq, K_);
        for (int j = 0; j < need; ++j) {
            int bi = -1, bv = 0x7fffffff;
            for (int t = 0; t < te; ++t) {
                int v = ties[t];
                if (v >= 0 && v < bv) { bv = v; bi = t; }
            }
            if (bi >= 0) { ties[bi] = -1; sel[have + j] = bv; }
            else         { sel[have + j] = sel[0]; }
        }
    }
    __syncthreads();

    // ---- rescore selected 512 (warp per dot)
    int lane = tid & 31, wid = tid >> 5;
    float biasv = *biasp;
    for (int s = wid; s < K_; s += 8) {
        int idx = sel[s];
        const float* v = neg + ((size_t)b * N_ + idx) * D_;
        float sum = 0.f;
#pragma unroll
        for (int q = 0; q < 4; ++q)
            sum = fmaf(spw[lane + q * 32], v[lane + q * 32], sum);
#pragma unroll
        for (int o = 16; o; o >>= 1)
            sum += __shfl_xor_sync(0xffffffffu, sum, o);
        if (lane == 0) sscore[s] = sum + biasv;
    }
    __syncthreads();

    // ---- softmax aggregation
    float sc;
    {
        float x = *scalep;
        sc = (x > 20.f) ? x : log1pf(expf(x));
    }
    float m = -INFINITY;
    for (int s = tid; s < K_; s += 256) m = fmaxf(m, sc * sscore[s]);
    red[tid] = m;
    __syncthreads();
    for (int o = 128; o; o >>= 1) {
        if (tid < o) red[tid] = fmaxf(red[tid], red[tid + o]);
        __syncthreads();
    }
    m = red[0];
    __syncthreads();

    float num = 0.f, den = 0.f;
    for (int s = tid; s < K_; s += 256) {
        float sv = sscore[s];
        float e = expf(sc * sv - m);
        num = fmaf(e, sv, num);
        den += e;
    }
    red[tid] = num;
    __syncthreads();
    for (int o = 128; o; o >>= 1) {
        if (tid < o) red[tid] += red[tid + o];
        __syncthreads();
    }
    num = red[0];
    __syncthreads();
    red[tid] = den;
    __syncthreads();
    for (int o = 128; o; o >>= 1) {
        if (tid < o) red[tid] += red[tid + o];
        __syncthreads();
    }
    den = red[0];

    if (tid == 0) out[row] = num / den;
}

// ---------------------------------------------------------------------------
extern "C" void kernel_launch(void* const* d_in, const int* in_sizes, int n_in,
                              void* d_out, int out_size) {
    const float* fea0  = (const float*)d_in[0];
    const float* neg   = (const float*)d_in[1];
    const float* W     = (const float*)d_in[2];
    const float* bias  = (const float*)d_in[3];
    const float* scale = (const float*)d_in[4];
    float* out = (float*)d_out;

    cudaFuncSetAttribute(gemm_kernel<0>,
                         cudaFuncAttributeMaxDynamicSharedMemorySize, SMEM_TC_BYTES);
    cudaFuncSetAttribute(gemm_kernel<1>,
                         cudaFuncAttributeMaxDynamicSharedMemorySize, SMEM_TC_BYTES);
    cudaFuncSetAttribute(select_kernel,
                         cudaFuncAttributeMaxDynamicSharedMemorySize, SEL_SMEM);

    // 1) sample GEMM: first 2048 columns
    gemm_kernel<0><<<dim3(SAMPN / TNB, B_), 256, SMEM_TC_BYTES>>>(fea0, neg);
    // 2) per-row threshold from sample + zero counters
    thresh_kernel<<<B_ * P_, 256>>>();
    // 3) full GEMM with candidate append
    gemm_kernel<1><<<dim3((N_ + TNB - 1) / TNB, B_), 256, SMEM_TC_BYTES>>>(fea0, neg);
    // 4) select + rescore + softmax
    select_kernel<<<B_ * P_, 256, SEL_SMEM>>>(fea0, neg, W, bias, scale, out);
}

// round 6
// speedup vs baseline: 1.2658x; 1.2658x over previous
#include <cuda_runtime.h>
#include <cuda_bf16.h>
#include <math.h>
#include <stdint.h>

#define B_ 8
#define P_ 100
#define N_ 50000
#define D_ 128
#define K_ 512
#define CAP 4096
#define SAMPN 2048
#define BUFCAP 1024
#define SELT 512

// Scratch (static device globals — no runtime allocation)
__device__ float g_fastsim[(size_t)B_ * P_ * N_];          // fallback-only
__device__ float g_sample[(size_t)B_ * P_ * SAMPN];        // 6.4 MB
__device__ unsigned g_lo[B_ * P_];
__device__ int g_cnt[B_ * P_];
__device__ unsigned long long g_cand[(size_t)B_ * P_ * CAP];  // 26 MB

__device__ __forceinline__ unsigned fkey(float f) {
    unsigned u = __float_as_uint(f);
    return (u & 0x80000000u) ? ~u : (u | 0x80000000u);   // monotonic increasing
}

// ---------------------------------------------------------------------------
// GEMM: pos @ neg^T tile, bf16x2-split on mma.sync (HMMA).
// CTA: 128(m) x 128(n), K=128. 8 warps, 64x32 each.
// MODE 0: dense store to g_sample. MODE 1: threshold + smem-buffered append.
// ---------------------------------------------------------------------------
#define TNB 128
#define TSTR 136
#define TILE_BYTES (128 * TSTR * 2)
#define SMEM_TC_BYTES (4 * TILE_BYTES + 4 * (128 + 1 + 128 + 128 + 2 * BUFCAP))

__device__ __forceinline__ uint32_t smem_u32(const void* p) {
    return (uint32_t)__cvta_generic_to_shared(p);
}
__device__ __forceinline__ void ldm_x4(uint32_t& r0, uint32_t& r1, uint32_t& r2, uint32_t& r3,
                                       uint32_t addr) {
    asm volatile("ldmatrix.sync.aligned.m8n8.x4.shared.b16 {%0,%1,%2,%3}, [%4];"
                 : "=r"(r0), "=r"(r1), "=r"(r2), "=r"(r3) : "r"(addr));
}
__device__ __forceinline__ void ldm_x2(uint32_t& r0, uint32_t& r1, uint32_t addr) {
    asm volatile("ldmatrix.sync.aligned.m8n8.x2.shared.b16 {%0,%1}, [%2];"
                 : "=r"(r0), "=r"(r1) : "r"(addr));
}
__device__ __forceinline__ void mma16816(float& c0, float& c1, float& c2, float& c3,
                                         uint32_t a0, uint32_t a1, uint32_t a2, uint32_t a3,
                                         uint32_t b0, uint32_t b1) {
    asm volatile("mma.sync.aligned.m16n8k16.row.col.f32.bf16.bf16.f32 "
                 "{%0,%1,%2,%3}, {%4,%5,%6,%7}, {%8,%9}, {%0,%1,%2,%3};"
                 : "+f"(c0), "+f"(c1), "+f"(c2), "+f"(c3)
                 : "r"(a0), "r"(a1), "r"(a2), "r"(a3), "r"(b0), "r"(b1));
}

template <int MODE>
__global__ void __launch_bounds__(256, 1) gemm_kernel(const float* __restrict__ pos,
                                                      const float* __restrict__ neg) {
    extern __shared__ __nv_bfloat16 smem[];
    __nv_bfloat16* Ah = smem;
    __nv_bfloat16* Al = smem + 128 * TSTR;
    __nv_bfloat16* Bh = smem + 2 * 128 * TSTR;
    __nv_bfloat16* Bl = smem + 3 * 128 * TSTR;

    int tid = threadIdx.x;
    int lane = tid & 31;
    int wid = tid >> 5;
    int b = blockIdx.y;
    int n0 = blockIdx.x * TNB;

    const float* Ab = pos + (size_t)b * P_ * D_;
    const float* Bb = neg + (size_t)b * N_ * D_;

    // ---- load + convert A (pad rows zero) and B (pad n zero)
#pragma unroll
    for (int i = 0; i < 16; ++i) {
        int f = i * 256 + tid;
        int r = f >> 5;
        int c = (f & 31) << 2;

        float4 va = make_float4(0.f, 0.f, 0.f, 0.f);
        if (r < P_) va = *(const float4*)(Ab + (size_t)r * D_ + c);
        __nv_bfloat162 h0 = __float22bfloat162_rn(make_float2(va.x, va.y));
        __nv_bfloat162 h1 = __float22bfloat162_rn(make_float2(va.z, va.w));
        float2 hf0 = __bfloat1622float2(h0), hf1 = __bfloat1622float2(h1);
        __nv_bfloat162 l0 = __float22bfloat162_rn(make_float2(va.x - hf0.x, va.y - hf0.y));
        __nv_bfloat162 l1 = __float22bfloat162_rn(make_float2(va.z - hf1.x, va.w - hf1.y));
        *(uint2*)(Ah + r * TSTR + c) = make_uint2(*(uint32_t*)&h0, *(uint32_t*)&h1);
        *(uint2*)(Al + r * TSTR + c) = make_uint2(*(uint32_t*)&l0, *(uint32_t*)&l1);

        int n = n0 + r;
        float4 vb = make_float4(0.f, 0.f, 0.f, 0.f);
        if (n < N_) vb = *(const float4*)(Bb + (size_t)n * D_ + c);
        h0 = __float22bfloat162_rn(make_float2(vb.x, vb.y));
        h1 = __float22bfloat162_rn(make_float2(vb.z, vb.w));
        hf0 = __bfloat1622float2(h0); hf1 = __bfloat1622float2(h1);
        l0 = __float22bfloat162_rn(make_float2(vb.x - hf0.x, vb.y - hf0.y));
        l1 = __float22bfloat162_rn(make_float2(vb.z - hf1.x, vb.w - hf1.y));
        *(uint2*)(Bh + r * TSTR + c) = make_uint2(*(uint32_t*)&h0, *(uint32_t*)&h1);
        *(uint2*)(Bl + r * TSTR + c) = make_uint2(*(uint32_t*)&l0, *(uint32_t*)&l1);
    }
    __syncthreads();

    int wm = wid >> 2;
    int wn = wid & 3;
    int mbase = wm * 64;
    int nbase = wn * 32;

    float c[4][4][4];
#pragma unroll
    for (int i = 0; i < 4; ++i)
#pragma unroll
        for (int j = 0; j < 4; ++j)
#pragma unroll
            for (int q = 0; q < 4; ++q) c[i][j][q] = 0.f;

    const __nv_bfloat16* pA[3] = {Ah, Ah, Al};
    const __nv_bfloat16* pB[3] = {Bh, Bl, Bh};

#pragma unroll
    for (int pr = 0; pr < 3; ++pr) {
        uint32_t abase = smem_u32(pA[pr]);
        uint32_t bbase = smem_u32(pB[pr]);
        uint32_t aoff = abase + (uint32_t)(lane & 15) * (TSTR * 2) + (uint32_t)(lane >> 4) * 16;
        uint32_t boff = bbase + (uint32_t)(lane & 7) * (TSTR * 2) + (uint32_t)((lane >> 3) & 1) * 16;

#pragma unroll
        for (int kc = 0; kc < 8; ++kc) {
            uint32_t kb = kc * 32;
            uint32_t a0[4], a1[4], a2[4], a3[4];
#pragma unroll
            for (int i = 0; i < 4; ++i)
                ldm_x4(a0[i], a1[i], a2[i], a3[i],
                       aoff + (uint32_t)(mbase + i * 16) * (TSTR * 2) + kb);
            uint32_t b0[4], b1[4];
#pragma unroll
            for (int j = 0; j < 4; ++j)
                ldm_x2(b0[j], b1[j],
                       boff + (uint32_t)(nbase + j * 8) * (TSTR * 2) + kb);
#pragma unroll
            for (int i = 0; i < 4; ++i)
#pragma unroll
                for (int j = 0; j < 4; ++j)
                    mma16816(c[i][j][0], c[i][j][1], c[i][j][2], c[i][j][3],
                             a0[i], a1[i], a2[i], a3[i], b0[j], b1[j]);
        }
    }

    // ---- epilogue
    int mrow0 = mbase + (lane >> 2);
    int ncol0 = n0 + nbase + (lane & 3) * 2;

    if (MODE == 0) {
#pragma unroll
        for (int i = 0; i < 4; ++i) {
            int m0 = mrow0 + i * 16;
            int m1 = m0 + 8;
#pragma unroll
            for (int j = 0; j < 4; ++j) {
                int nc = ncol0 + j * 8;
                if (m0 < P_)
                    *(float2*)(g_sample + (size_t)(b * P_ + m0) * SAMPN + nc) =
                        make_float2(c[i][j][0], c[i][j][1]);
                if (m1 < P_)
                    *(float2*)(g_sample + (size_t)(b * P_ + m1) * SAMPN + nc) =
                        make_float2(c[i][j][2], c[i][j][3]);
            }
        }
    } else {
        __syncthreads();
        // smem reuse after compute
        uint32_t* lo_s   = (uint32_t*)smem;          // [128]
        uint32_t* s_scnt = lo_s + 128;               // [1]
        uint32_t* s_hist = s_scnt + 1;               // [128]
        uint32_t* s_base = s_hist + 128;             // [128]
        uint32_t* buf_k  = s_base + 128;             // [BUFCAP]
        uint32_t* buf_rn = buf_k + BUFCAP;           // [BUFCAP]

        if (tid < 128) {
            lo_s[tid] = (tid < P_) ? g_lo[b * P_ + tid] : 0xFFFFFFFFu;
            s_hist[tid] = 0;
        }
        if (tid == 0) *s_scnt = 0;
        __syncthreads();

        // warp-ballot aggregated push of candidates into smem buffer
#pragma unroll
        for (int i = 0; i < 4; ++i) {
#pragma unroll
            for (int j = 0; j < 4; ++j) {
#pragma unroll
                for (int q = 0; q < 4; ++q) {
                    int m = mrow0 + i * 16 + (q >> 1) * 8;        // q<2 -> m0, q>=2 -> m1
                    int n = ncol0 + j * 8 + (q & 1);
                    float v = c[i][j][q];
                    bool pred = false;
                    unsigned k = 0;
                    if (m < P_ && n < N_) {
                        k = fkey(v);
                        pred = (k >= lo_s[m]);
                    }
                    unsigned msk = __ballot_sync(0xffffffffu, pred);
                    if (msk) {
                        int leader = __ffs(msk) - 1;
                        unsigned base = 0;
                        if (lane == leader) base = atomicAdd(s_scnt, __popc(msk));
                        base = __shfl_sync(0xffffffffu, base, leader);
                        if (pred) {
                            unsigned pos = base + __popc(msk & ((1u << lane) - 1u));
                            if (pos < BUFCAP) {
                                buf_k[pos]  = k;
                                buf_rn[pos] = ((unsigned)m << 16) | (unsigned)n;
                            }
                        }
                    }
                }
            }
        }
        __syncthreads();

        unsigned raw = *s_scnt;
        unsigned total = raw > BUFCAP ? BUFCAP : raw;
        bool ovf = (raw > BUFCAP);

        // per-row histogram
        for (unsigned i = tid; i < total; i += 256)
            atomicAdd(&s_hist[buf_rn[i] >> 16], 1u);
        __syncthreads();

        // reserve per-row space in g_cand with ONE global atomic per row
        if (tid < P_) {
            unsigned h = s_hist[tid];
            unsigned add = h + (ovf ? (CAP + 1) : 0);
            s_base[tid] = add ? (unsigned)atomicAdd(&g_cnt[b * P_ + tid], (int)add) : 0u;
            s_hist[tid] = 0;    // reuse as running offset
        }
        __syncthreads();

        // scatter (grouped per row)
        for (unsigned i = tid; i < total; i += 256) {
            unsigned rn = buf_rn[i];
            int m = rn >> 16;
            unsigned off = atomicAdd(&s_hist[m], 1u);
            unsigned pos = s_base[m] + off;
            if (pos < CAP)
                g_cand[(size_t)(b * P_ + m) * CAP + pos] =
                    ((unsigned long long)buf_k[i] << 32) | (rn & 0xFFFFu);
        }
    }
}

// ---------------------------------------------------------------------------
// shared radix helper (works for any blockDim >= 256)
// ---------------------------------------------------------------------------
__device__ void scan_bins(unsigned* hist, unsigned* csum, int nbins, int kr,
                          int sh, unsigned prefix,
                          unsigned* s_thresh, int* s_kr, int tid) {
    int chunks = nbins >> 3;
    if (tid < chunks) {
        unsigned s = 0;
#pragma unroll
        for (int i = 0; i < 8; ++i) s += hist[tid * 8 + i];
        csum[tid] = s;
    }
    __syncthreads();
    if (tid == 0) {
        unsigned cum = 0;
        int c = chunks - 1;
        for (; c > 0; --c) {
            if (cum + csum[c] >= (unsigned)kr) break;
            cum += csum[c];
        }
        int bin = c * 8 + 7;
        for (; bin > c * 8; --bin) {
            if (cum + hist[bin] >= (unsigned)kr) break;
            cum += hist[bin];
        }
        *s_thresh = prefix | ((unsigned)bin << sh);
        *s_kr = kr - (int)cum;
    }
    __syncthreads();
}

// ---------------------------------------------------------------------------
// Threshold kernel: lo[row] = exact 64th-largest key of sample row; zero cnt.
// ---------------------------------------------------------------------------
__global__ void __launch_bounds__(256) thresh_kernel() {
    int row = blockIdx.x;
    int tid = threadIdx.x;
    const float* sim = g_sample + (size_t)row * SAMPN;

    __shared__ unsigned hist[2048];
    __shared__ unsigned csum[256];
    __shared__ unsigned s_thresh;
    __shared__ int s_kr;

    unsigned skey[8];
#pragma unroll
    for (int q = 0; q < 2; ++q) {
        float4 v = *(const float4*)(sim + tid * 8 + q * 4);
        skey[q * 4 + 0] = fkey(v.x); skey[q * 4 + 1] = fkey(v.y);
        skey[q * 4 + 2] = fkey(v.z); skey[q * 4 + 3] = fkey(v.w);
    }
    const int      shifts[3] = {21, 10, 0};
    const unsigned masks[3]  = {0x7FFu, 0x7FFu, 0x3FFu};
    const int      nbinsv[3] = {2048, 2048, 1024};
    unsigned prefix = 0, pmask = 0;
    int kr = 64;
    for (int pass = 0; pass < 3; ++pass) {
        int sh = shifts[pass]; unsigned mk = masks[pass];
#pragma unroll
        for (int i = 0; i < 8; ++i) hist[tid * 8 + i] = 0;
        __syncthreads();
#pragma unroll
        for (int i = 0; i < 8; ++i) {
            unsigned u = skey[i];
            if ((u & pmask) == prefix) atomicAdd(&hist[(u >> sh) & mk], 1u);
        }
        __syncthreads();
        scan_bins(hist, csum, nbinsv[pass], kr, sh, prefix, &s_thresh, &s_kr, tid);
        prefix = s_thresh; kr = s_kr; pmask |= mk << sh;
        __syncthreads();
    }
    if (tid == 0) {
        g_lo[row] = prefix;
        g_cnt[row] = 0;
    }
}

// ---------------------------------------------------------------------------
// Select kernel (512 threads): candidates -> exact top-512 -> rescore -> agg.
// ---------------------------------------------------------------------------
#define SEL_SMEM ((2048 + 256 + CAP + CAP + K_ + K_ + K_ + 128 + 128 + SELT) * 4)

__global__ void __launch_bounds__(SELT) select_kernel(const float* __restrict__ pos,
                                                      const float* __restrict__ neg,
                                                      const float* __restrict__ Wm,
                                                      const float* __restrict__ biasp,
                                                      const float* __restrict__ scalep,
                                                      float* __restrict__ out) {
    int row = blockIdx.x;
    int b = row / P_;
    int tid = threadIdx.x;

    extern __shared__ unsigned dsm[];
    unsigned* hist  = dsm;                 // 2048
    unsigned* csum  = hist + 2048;         // 256
    unsigned* candk = csum + 256;          // CAP
    int*      candi = (int*)(candk + CAP); // CAP
    int*      sel   = candi + CAP;         // K_
    float*    sscore = (float*)(sel + K_); // K_
    int*      ties  = (int*)(sscore + K_); // K_
    float*    ppos  = (float*)(ties + K_); // 128
    float*    spw   = ppos + 128;          // 128
    float*    red   = spw + 128;           // SELT

    __shared__ unsigned s_thresh;
    __shared__ int s_kr, s_cntgt, s_cnteq;

    // ---- pos row + posW
    if (tid < D_) ppos[tid] = pos[(size_t)row * D_ + tid];
    __syncthreads();
    if (tid < D_) {
        float acc = 0.f;
#pragma unroll 8
        for (int d = 0; d < D_; ++d)
            acc = fmaf(ppos[d], Wm[d * D_ + tid], acc);
        spw[tid] = acc;
    }

    int cnt = g_cnt[row];
    bool fb = (cnt < K_) || (cnt > CAP);

    if (!fb) {
        for (int i = tid; i < cnt; i += SELT) {
            unsigned long long v = g_cand[(size_t)row * CAP + i];
            candk[i] = (unsigned)(v >> 32);
            candi[i] = (int)(unsigned)v;
        }
    } else {
        __syncthreads();   // ppos ready
        float* simw = g_fastsim + (size_t)row * N_;
        for (int n = tid; n < N_; n += SELT) {
            const float* v = neg + ((size_t)b * N_ + n) * D_;
            float s = 0.f;
#pragma unroll 8
            for (int d = 0; d < D_; ++d) s = fmaf(ppos[d], v[d], s);
            simw[n] = s;
        }
    }
    __syncthreads();

    const int      shifts[3] = {21, 10, 0};
    const unsigned masks[3]  = {0x7FFu, 0x7FFu, 0x3FFu};
    const int      nbinsv[3] = {2048, 2048, 1024};

    // ---- exact 512th-largest key -> uth
    unsigned prefix = 0, pmask = 0;
    int kr = K_;
    const float* simr = g_fastsim + (size_t)row * N_;
    for (int pass = 0; pass < 3; ++pass) {
        int sh = shifts[pass]; unsigned mk = masks[pass];
        for (int i = tid; i < 2048; i += SELT) hist[i] = 0;
        __syncthreads();
        if (!fb) {
            for (int i = tid; i < cnt; i += SELT) {
                unsigned u = candk[i];
                if ((u & pmask) == prefix) atomicAdd(&hist[(u >> sh) & mk], 1u);
            }
        } else {
            for (int n = tid; n < N_; n += SELT) {
                unsigned u = fkey(simr[n]);
                if ((u & pmask) == prefix) atomicAdd(&hist[(u >> sh) & mk], 1u);
            }
        }
        __syncthreads();
        scan_bins(hist, csum, nbinsv[pass], kr, sh, prefix, &s_thresh, &s_kr, tid);
        prefix = s_thresh; kr = s_kr; pmask |= mk << sh;
        __syncthreads();
    }
    unsigned uth = prefix;

    // ---- collect winners (> uth) and ties (== uth)
    if (tid == 0) { s_cntgt = 0; s_cnteq = 0; }
    __syncthreads();
    if (!fb) {
        for (int i = tid; i < cnt; i += SELT) {
            unsigned u = candk[i];
            if (u > uth) {
                int q = atomicAdd(&s_cntgt, 1);
                sel[q] = candi[i];
            } else if (u == uth) {
                int q = atomicAdd(&s_cnteq, 1);
                if (q < K_) ties[q] = candi[i];
            }
        }
    } else {
        for (int n = tid; n < N_; n += SELT) {
            unsigned u = fkey(simr[n]);
            if (u > uth) {
                int q = atomicAdd(&s_cntgt, 1);
                sel[q] = n;
            } else if (u == uth) {
                int q = atomicAdd(&s_cnteq, 1);
                if (q < K_) ties[q] = n;
            }
        }
    }
    __syncthreads();
    if (tid == 0) {
        int have = s_cntgt;
        int need = K_ - have;
        int te = min(s_cnteq, K_);
        for (int j = 0; j < need; ++j) {
            int bi = -1, bv = 0x7fffffff;
            for (int t = 0; t < te; ++t) {
                int v = ties[t];
                if (v >= 0 && v < bv) { bv = v; bi = t; }
            }
            if (bi >= 0) { ties[bi] = -1; sel[have + j] = bv; }
            else         { sel[have + j] = sel[0]; }
        }
    }
    __syncthreads();

    // ---- rescore selected 512 (warp per dot, 16 warps)
    int lane = tid & 31, wid = tid >> 5;
    float biasv = *biasp;
    for (int s = wid; s < K_; s += SELT / 32) {
        int idx = sel[s];
        const float* v = neg + ((size_t)b * N_ + idx) * D_;
        float sum = 0.f;
#pragma unroll
        for (int q = 0; q < 4; ++q)
            sum = fmaf(spw[lane + q * 32], v[lane + q * 32], sum);
#pragma unroll
        for (int o = 16; o; o >>= 1)
            sum += __shfl_xor_sync(0xffffffffu, sum, o);
        if (lane == 0) sscore[s] = sum + biasv;
    }
    __syncthreads();

    // ---- softmax aggregation
    float sc;
    {
        float x = *scalep;
        sc = (x > 20.f) ? x : log1pf(expf(x));
    }
    float m = -INFINITY;
    for (int s = tid; s < K_; s += SELT) m = fmaxf(m, sc * sscore[s]);
    red[tid] = m;
    __syncthreads();
    for (int o = SELT / 2; o; o >>= 1) {
        if (tid < o) red[tid] = fmaxf(red[tid], red[tid + o]);
        __syncthreads();
    }
    m = red[0];
    __syncthreads();

    float num = 0.f, den = 0.f;
    for (int s = tid; s < K_; s += SELT) {
        float sv = sscore[s];
        float e = expf(sc * sv - m);
        num = fmaf(e, sv, num);
        den += e;
    }
    red[tid] = num;
    __syncthreads();
    for (int o = SELT / 2; o; o >>= 1) {
        if (tid < o) red[tid] += red[tid + o];
        __syncthreads();
    }
    num = red[0];
    __syncthreads();
    red[tid] = den;
    __syncthreads();
    for (int o = SELT / 2; o; o >>= 1) {
        if (tid < o) red[tid] += red[tid + o];
        __syncthreads();
    }
    den = red[0];

    if (tid == 0) out[row] = num / den;
}

// ---------------------------------------------------------------------------
extern "C" void kernel_launch(void* const* d_in, const int* in_sizes, int n_in,
                              void* d_out, int out_size) {
    const float* fea0  = (const float*)d_in[0];
    const float* neg   = (const float*)d_in[1];
    const float* W     = (const float*)d_in[2];
    const float* bias  = (const float*)d_in[3];
    const float* scale = (const float*)d_in[4];
    float* out = (float*)d_out;

    cudaFuncSetAttribute(gemm_kernel<0>,
                         cudaFuncAttributeMaxDynamicSharedMemorySize, SMEM_TC_BYTES);
    cudaFuncSetAttribute(gemm_kernel<1>,
                         cudaFuncAttributeMaxDynamicSharedMemorySize, SMEM_TC_BYTES);
    cudaFuncSetAttribute(select_kernel,
                         cudaFuncAttributeMaxDynamicSharedMemorySize, SEL_SMEM);

    // 1) sample GEMM: first 2048 columns
    gemm_kernel<0><<<dim3(SAMPN / TNB, B_), 256, SMEM_TC_BYTES>>>(fea0, neg);
    // 2) per-row threshold from sample + zero counters
    thresh_kernel<<<B_ * P_, 256>>>();
    // 3) full GEMM with smem-buffered candidate append
    gemm_kernel<1><<<dim3((N_ + TNB - 1) / TNB, B_), 256, SMEM_TC_BYTES>>>(fea0, neg);
    // 4) select + rescore + softmax
    select_kernel<<<B_ * P_, SELT, SEL_SMEM>>>(fea0, neg, W, bias, scale, out);
}

// round 7
// speedup vs baseline: 1.8743x; 1.4807x over previous
#include <cuda_runtime.h>
#include <cuda_bf16.h>
#include <math.h>
#include <stdint.h>

#define B_ 8
#define P_ 100
#define N_ 50000
#define D_ 128
#define K_ 512
#define CAP 4096
#define SAMPN 2048
#define BUFW 256
#define SELT 512
#define MARGIN 0.5f

// Scratch (static device globals — no runtime allocation)
__device__ float g_fastsim[(size_t)B_ * P_ * N_];      // fallback-only
__device__ float g_sample[(size_t)B_ * P_ * SAMPN];    // 6.4 MB (hi*hi approx)
__device__ float g_lof[B_ * P_];                       // float thresholds
__device__ int g_cnt[B_ * P_];
__device__ int g_cand[(size_t)B_ * P_ * CAP];          // candidate indices (13 MB)

__device__ __forceinline__ unsigned fkey(float f) {
    unsigned u = __float_as_uint(f);
    return (u & 0x80000000u) ? ~u : (u | 0x80000000u);   // monotonic increasing
}
__device__ __forceinline__ float inv_fkey(unsigned k) {
    return (k & 0x80000000u) ? __uint_as_float(k ^ 0x80000000u)
                             : __uint_as_float(~k);
}

// ---------------------------------------------------------------------------
// GEMM (hi*hi approx): pos @ neg^T tile on mma.sync bf16.
// CTA: 128(m) x 128(n), K=128. 8 warps, 64x32 each. 2 smem tiles (70 KB).
// MODE 0: dense store to g_sample. MODE 1: margin filter + index append.
// ---------------------------------------------------------------------------
#define TNB 128
#define TSTR 136
#define TILE_BYTES (128 * TSTR * 2)
#define SMEM_TC_BYTES (2 * TILE_BYTES)

__device__ __forceinline__ uint32_t smem_u32(const void* p) {
    return (uint32_t)__cvta_generic_to_shared(p);
}
__device__ __forceinline__ void ldm_x4(uint32_t& r0, uint32_t& r1, uint32_t& r2, uint32_t& r3,
                                       uint32_t addr) {
    asm volatile("ldmatrix.sync.aligned.m8n8.x4.shared.b16 {%0,%1,%2,%3}, [%4];"
                 : "=r"(r0), "=r"(r1), "=r"(r2), "=r"(r3) : "r"(addr));
}
__device__ __forceinline__ void ldm_x2(uint32_t& r0, uint32_t& r1, uint32_t addr) {
    asm volatile("ldmatrix.sync.aligned.m8n8.x2.shared.b16 {%0,%1}, [%2];"
                 : "=r"(r0), "=r"(r1) : "r"(addr));
}
__device__ __forceinline__ void mma16816(float& c0, float& c1, float& c2, float& c3,
                                         uint32_t a0, uint32_t a1, uint32_t a2, uint32_t a3,
                                         uint32_t b0, uint32_t b1) {
    asm volatile("mma.sync.aligned.m16n8k16.row.col.f32.bf16.bf16.f32 "
                 "{%0,%1,%2,%3}, {%4,%5,%6,%7}, {%8,%9}, {%0,%1,%2,%3};"
                 : "+f"(c0), "+f"(c1), "+f"(c2), "+f"(c3)
                 : "r"(a0), "r"(a1), "r"(a2), "r"(a3), "r"(b0), "r"(b1));
}

template <int MODE>
__global__ void __launch_bounds__(256) gemm_kernel(const float* __restrict__ pos,
                                                   const float* __restrict__ neg) {
    extern __shared__ __nv_bfloat16 smem[];
    __nv_bfloat16* Ah = smem;
    __nv_bfloat16* Bh = smem + 128 * TSTR;

    int tid = threadIdx.x;
    int lane = tid & 31;
    int wid = tid >> 5;
    int b = blockIdx.y;
    int n0 = blockIdx.x * TNB;

    const float* Ab = pos + (size_t)b * P_ * D_;
    const float* Bb = neg + (size_t)b * N_ * D_;

    // ---- load + convert (hi only); pad rows / pad n -> zero
#pragma unroll
    for (int i = 0; i < 16; ++i) {
        int f = i * 256 + tid;
        int r = f >> 5;
        int c = (f & 31) << 2;

        float4 va = make_float4(0.f, 0.f, 0.f, 0.f);
        if (r < P_) va = *(const float4*)(Ab + (size_t)r * D_ + c);
        __nv_bfloat162 a0 = __float22bfloat162_rn(make_float2(va.x, va.y));
        __nv_bfloat162 a1 = __float22bfloat162_rn(make_float2(va.z, va.w));
        *(uint2*)(Ah + r * TSTR + c) = make_uint2(*(uint32_t*)&a0, *(uint32_t*)&a1);

        int n = n0 + r;
        float4 vb = make_float4(0.f, 0.f, 0.f, 0.f);
        if (n < N_) vb = *(const float4*)(Bb + (size_t)n * D_ + c);
        __nv_bfloat162 b0 = __float22bfloat162_rn(make_float2(vb.x, vb.y));
        __nv_bfloat162 b1 = __float22bfloat162_rn(make_float2(vb.z, vb.w));
        *(uint2*)(Bh + r * TSTR + c) = make_uint2(*(uint32_t*)&b0, *(uint32_t*)&b1);
    }
    __syncthreads();

    int wm = wid >> 2;
    int wn = wid & 3;
    int mbase = wm * 64;
    int nbase = wn * 32;

    float c[4][4][4];
#pragma unroll
    for (int i = 0; i < 4; ++i)
#pragma unroll
        for (int j = 0; j < 4; ++j)
#pragma unroll
            for (int q = 0; q < 4; ++q) c[i][j][q] = 0.f;

    {
        uint32_t abase = smem_u32(Ah);
        uint32_t bbase = smem_u32(Bh);
        uint32_t aoff = abase + (uint32_t)(lane & 15) * (TSTR * 2) + (uint32_t)(lane >> 4) * 16;
        uint32_t boff = bbase + (uint32_t)(lane & 7) * (TSTR * 2) + (uint32_t)((lane >> 3) & 1) * 16;

#pragma unroll
        for (int kc = 0; kc < 8; ++kc) {
            uint32_t kb = kc * 32;
            uint32_t a0[4], a1[4], a2[4], a3[4];
#pragma unroll
            for (int i = 0; i < 4; ++i)
                ldm_x4(a0[i], a1[i], a2[i], a3[i],
                       aoff + (uint32_t)(mbase + i * 16) * (TSTR * 2) + kb);
            uint32_t b0[4], b1[4];
#pragma unroll
            for (int j = 0; j < 4; ++j)
                ldm_x2(b0[j], b1[j],
                       boff + (uint32_t)(nbase + j * 8) * (TSTR * 2) + kb);
#pragma unroll
            for (int i = 0; i < 4; ++i)
#pragma unroll
                for (int j = 0; j < 4; ++j)
                    mma16816(c[i][j][0], c[i][j][1], c[i][j][2], c[i][j][3],
                             a0[i], a1[i], a2[i], a3[i], b0[j], b1[j]);
        }
    }

    // ---- epilogue
    int mrow0 = mbase + (lane >> 2);
    int ncol0 = n0 + nbase + (lane & 3) * 2;

    if (MODE == 0) {
#pragma unroll
        for (int i = 0; i < 4; ++i) {
            int m0 = mrow0 + i * 16;
            int m1 = m0 + 8;
#pragma unroll
            for (int j = 0; j < 4; ++j) {
                int nc = ncol0 + j * 8;
                if (m0 < P_)
                    *(float2*)(g_sample + (size_t)(b * P_ + m0) * SAMPN + nc) =
                        make_float2(c[i][j][0], c[i][j][1]);
                if (m1 < P_)
                    *(float2*)(g_sample + (size_t)(b * P_ + m1) * SAMPN + nc) =
                        make_float2(c[i][j][2], c[i][j][3]);
            }
        }
    } else {
        __syncthreads();   // tiles dead; reuse smem
        float*    lof    = (float*)smem;            // [128]
        uint32_t* s_wcnt = (uint32_t*)(lof + 128);  // [8]
        uint32_t* s_hist = s_wcnt + 8;              // [128]
        uint32_t* s_base = s_hist + 128;            // [128]
        uint32_t* s_ovf  = s_base + 128;            // [1]
        uint32_t* bufs   = s_ovf + 1;               // [8][BUFW]

        if (tid < 128) {
            lof[tid] = (tid < P_) ? g_lof[b * P_ + tid] : 3.4e38f;
            s_hist[tid] = 0;
        }
        if (tid == 0) *s_ovf = 0;
        __syncthreads();

        // per-warp atomic-free compaction
        unsigned wcnt = 0;
        uint32_t* mybuf = bufs + wid * BUFW;
        unsigned lmask = (1u << lane) - 1u;
#pragma unroll
        for (int i = 0; i < 4; ++i) {
#pragma unroll
            for (int j = 0; j < 4; ++j) {
#pragma unroll
                for (int q = 0; q < 4; ++q) {
                    int m = mrow0 + i * 16 + (q >> 1) * 8;
                    int n = ncol0 + j * 8 + (q & 1);
                    bool pred = (m < P_) && (n < N_) && (c[i][j][q] >= lof[m & 127]);
                    unsigned msk = __ballot_sync(0xffffffffu, pred);
                    if (pred) {
                        unsigned pos = wcnt + __popc(msk & lmask);
                        if (pos < BUFW) mybuf[pos] = ((unsigned)m << 16) | (unsigned)n;
                    }
                    wcnt += __popc(msk);
                }
            }
        }
        if (lane == 0) {
            s_wcnt[wid] = wcnt > BUFW ? BUFW : wcnt;
            if (wcnt > BUFW) *s_ovf = 1;
        }
        __syncthreads();

        // per-row histogram over all warp segments
#pragma unroll
        for (int w = 0; w < 8; ++w) {
            unsigned cw = s_wcnt[w];
            for (unsigned i = tid; i < cw; i += 256)
                atomicAdd(&s_hist[bufs[w * BUFW + i] >> 16], 1u);
        }
        __syncthreads();

        // reserve g_cand space: ONE global atomic per row
        unsigned ovf = *s_ovf;
        if (tid < P_) {
            unsigned add = s_hist[tid] + (ovf ? (CAP + 1) : 0);
            s_base[tid] = add ? (unsigned)atomicAdd(&g_cnt[b * P_ + tid], (int)add) : 0u;
            s_hist[tid] = 0;
        }
        __syncthreads();

        // scatter indices
#pragma unroll
        for (int w = 0; w < 8; ++w) {
            unsigned cw = s_wcnt[w];
            for (unsigned i = tid; i < cw; i += 256) {
                unsigned e = bufs[w * BUFW + i];
                unsigned m = e >> 16;
                unsigned off = atomicAdd(&s_hist[m], 1u);
                unsigned pos = s_base[m] + off;
                if (pos < CAP)
                    g_cand[(size_t)(b * P_ + m) * CAP + pos] = (int)(e & 0xFFFFu);
            }
        }
    }
}

// ---------------------------------------------------------------------------
// shared radix helper
// ---------------------------------------------------------------------------
__device__ void scan_bins(unsigned* hist, unsigned* csum, int nbins, int kr,
                          int sh, unsigned prefix,
                          unsigned* s_thresh, int* s_kr, int tid) {
    int chunks = nbins >> 3;
    if (tid < chunks) {
        unsigned s = 0;
#pragma unroll
        for (int i = 0; i < 8; ++i) s += hist[tid * 8 + i];
        csum[tid] = s;
    }
    __syncthreads();
    if (tid == 0) {
        unsigned cum = 0;
        int c = chunks - 1;
        for (; c > 0; --c) {
            if (cum + csum[c] >= (unsigned)kr) break;
            cum += csum[c];
        }
        int bin = c * 8 + 7;
        for (; bin > c * 8; --bin) {
            if (cum + hist[bin] >= (unsigned)kr) break;
            cum += hist[bin];
        }
        *s_thresh = prefix | ((unsigned)bin << sh);
        *s_kr = kr - (int)cum;
    }
    __syncthreads();
}

// ---------------------------------------------------------------------------
// Threshold kernel: g_lof[row] = (64th-largest of sample) - MARGIN; zero cnt.
// ---------------------------------------------------------------------------
__global__ void __launch_bounds__(256) thresh_kernel() {
    int row = blockIdx.x;
    int tid = threadIdx.x;
    const float* sim = g_sample + (size_t)row * SAMPN;

    __shared__ unsigned hist[2048];
    __shared__ unsigned csum[256];
    __shared__ unsigned s_thresh;
    __shared__ int s_kr;

    unsigned skey[8];
#pragma unroll
    for (int q = 0; q < 2; ++q) {
        float4 v = *(const float4*)(sim + tid * 8 + q * 4);
        skey[q * 4 + 0] = fkey(v.x); skey[q * 4 + 1] = fkey(v.y);
        skey[q * 4 + 2] = fkey(v.z); skey[q * 4 + 3] = fkey(v.w);
    }
    const int      shifts[3] = {21, 10, 0};
    const unsigned masks[3]  = {0x7FFu, 0x7FFu, 0x3FFu};
    const int      nbinsv[3] = {2048, 2048, 1024};
    unsigned prefix = 0, pmask = 0;
    int kr = 64;
    for (int pass = 0; pass < 3; ++pass) {
        int sh = shifts[pass]; unsigned mk = masks[pass];
#pragma unroll
        for (int i = 0; i < 8; ++i) hist[tid * 8 + i] = 0;
        __syncthreads();
#pragma unroll
        for (int i = 0; i < 8; ++i) {
            unsigned u = skey[i];
            if ((u & pmask) == prefix) atomicAdd(&hist[(u >> sh) & mk], 1u);
        }
        __syncthreads();
        scan_bins(hist, csum, nbinsv[pass], kr, sh, prefix, &s_thresh, &s_kr, tid);
        prefix = s_thresh; kr = s_kr; pmask |= mk << sh;
        __syncthreads();
    }
    if (tid == 0) {
        g_lof[row] = inv_fkey(prefix) - MARGIN;
        g_cnt[row] = 0;
    }
}

// ---------------------------------------------------------------------------
// Select (512 thr): exact fp32 fast+bilinear dots on candidates -> top-512 ->
// softmax aggregation.
// ---------------------------------------------------------------------------
#define SEL_SMEM ((2048 + 256 + 3 * CAP + 2 * K_ + 2 * 128 + SELT) * 4)

__global__ void __launch_bounds__(SELT) select_kernel(const float* __restrict__ pos,
                                                      const float* __restrict__ neg,
                                                      const float* __restrict__ Wm,
                                                      const float* __restrict__ biasp,
                                                      const float* __restrict__ scalep,
                                                      float* __restrict__ out) {
    int row = blockIdx.x;
    int b = row / P_;
    int tid = threadIdx.x;

    extern __shared__ unsigned dsm[];
    unsigned* hist  = dsm;                  // 2048
    unsigned* csum  = hist + 2048;          // 256
    int*      candn = (int*)(csum + 256);   // CAP
    unsigned* candk = (unsigned*)(candn + CAP); // CAP
    float*    candb = (float*)(candk + CAP);    // CAP
    int*      sel   = (int*)(candb + CAP);  // K_
    int*      ties  = sel + K_;             // K_
    float*    ppos  = (float*)(ties + K_);  // 128
    float*    spw   = ppos + 128;           // 128
    float*    red   = spw + 128;            // SELT

    __shared__ unsigned s_thresh;
    __shared__ int s_kr, s_cntgt, s_cnteq;
    __shared__ float sscore[K_];

    if (tid < D_) ppos[tid] = pos[(size_t)row * D_ + tid];
    __syncthreads();
    if (tid < D_) {
        float acc = 0.f;
#pragma unroll 8
        for (int d = 0; d < D_; ++d)
            acc = fmaf(ppos[d], Wm[d * D_ + tid], acc);
        spw[tid] = acc;
    }

    int cnt = g_cnt[row];
    bool fb = (cnt < K_) || (cnt > CAP);

    int lane = tid & 31, wid = tid >> 5;

    if (!fb) {
        for (int i = tid; i < cnt; i += SELT)
            candn[i] = g_cand[(size_t)row * CAP + i];
        __syncthreads();

        // exact fp32 dots per candidate (warp per candidate)
        float4 p4 = ((const float4*)ppos)[lane];
        float4 w4 = ((const float4*)spw)[lane];
        for (int cd = wid; cd < cnt; cd += SELT / 32) {
            int idx = candn[cd];
            float4 v = ((const float4*)(neg + ((size_t)b * N_ + idx) * D_))[lane];
            float sf = v.x * p4.x + v.y * p4.y + v.z * p4.z + v.w * p4.w;
            float sb = v.x * w4.x + v.y * w4.y + v.z * w4.z + v.w * w4.w;
#pragma unroll
            for (int o = 16; o; o >>= 1) {
                sf += __shfl_xor_sync(0xffffffffu, sf, o);
                sb += __shfl_xor_sync(0xffffffffu, sb, o);
            }
            if (lane == 0) {
                candk[cd] = fkey(sf);
                candb[cd] = sb;
            }
        }
    } else {
        __syncthreads();   // ppos ready
        float* simw = g_fastsim + (size_t)row * N_;
        for (int n = tid; n < N_; n += SELT) {
            const float* v = neg + ((size_t)b * N_ + n) * D_;
            float s = 0.f;
#pragma unroll 8
            for (int d = 0; d < D_; ++d) s = fmaf(ppos[d], v[d], s);
            simw[n] = s;
        }
    }
    __syncthreads();

    const int      shifts[3] = {21, 10, 0};
    const unsigned masks[3]  = {0x7FFu, 0x7FFu, 0x3FFu};
    const int      nbinsv[3] = {2048, 2048, 1024};

    // ---- exact 512th-largest fast key -> uth
    unsigned prefix = 0, pmask = 0;
    int kr = K_;
    const float* simr = g_fastsim + (size_t)row * N_;
    for (int pass = 0; pass < 3; ++pass) {
        int sh = shifts[pass]; unsigned mk = masks[pass];
        for (int i = tid; i < 2048; i += SELT) hist[i] = 0;
        __syncthreads();
        if (!fb) {
            for (int i = tid; i < cnt; i += SELT) {
                unsigned u = candk[i];
                if ((u & pmask) == prefix) atomicAdd(&hist[(u >> sh) & mk], 1u);
            }
        } else {
            for (int n = tid; n < N_; n += SELT) {
                unsigned u = fkey(simr[n]);
                if ((u & pmask) == prefix) atomicAdd(&hist[(u >> sh) & mk], 1u);
            }
        }
        __syncthreads();
        scan_bins(hist, csum, nbinsv[pass], kr, sh, prefix, &s_thresh, &s_kr, tid);
        prefix = s_thresh; kr = s_kr; pmask |= mk << sh;
        __syncthreads();
    }
    unsigned uth = prefix;

    // ---- collect winners (> uth) and ties (== uth)
    if (tid == 0) { s_cntgt = 0; s_cnteq = 0; }
    __syncthreads();
    if (!fb) {
        for (int i = tid; i < cnt; i += SELT) {
            unsigned u = candk[i];
            if (u > uth) {
                int q = atomicAdd(&s_cntgt, 1);
                sel[q] = i;                      // buffer index
            } else if (u == uth) {
                int q = atomicAdd(&s_cnteq, 1);
                if (q < K_) ties[q] = i;
            }
        }
    } else {
        for (int n = tid; n < N_; n += SELT) {
            unsigned u = fkey(simr[n]);
            if (u > uth) {
                int q = atomicAdd(&s_cntgt, 1);
                sel[q] = n;                      // direct n index
            } else if (u == uth) {
                int q = atomicAdd(&s_cnteq, 1);
                if (q < K_) ties[q] = n;
            }
        }
    }
    __syncthreads();
    if (tid == 0) {
        int have = s_cntgt;
        int need = K_ - have;
        int te = min(s_cnteq, K_);
        for (int j = 0; j < need; ++j) {
            int bi = -1; long long bv = 0x7fffffffLL;
            for (int t = 0; t < te; ++t) {
                int v = ties[t];
                if (v < 0) continue;
                long long key = fb ? (long long)v : (long long)candn[v];
                if (key < bv) { bv = key; bi = t; }
            }
            if (bi >= 0) { sel[have + j] = ties[bi]; ties[bi] = -1; }
            else         { sel[have + j] = sel[0]; }
        }
    }
    __syncthreads();

    // ---- scores of the 512 selected
    float biasv = *biasp;
    if (!fb) {
        for (int j = tid; j < K_; j += SELT)
            sscore[j] = candb[sel[j]] + biasv;
    } else {
        float4 w4 = ((const float4*)spw)[lane];
        for (int s = wid; s < K_; s += SELT / 32) {
            int idx = sel[s];
            float4 v = ((const float4*)(neg + ((size_t)b * N_ + idx) * D_))[lane];
            float sum = v.x * w4.x + v.y * w4.y + v.z * w4.z + v.w * w4.w;
#pragma unroll
            for (int o = 16; o; o >>= 1)
                sum += __shfl_xor_sync(0xffffffffu, sum, o);
            if (lane == 0) sscore[s] = sum + biasv;
        }
    }
    __syncthreads();

    // ---- softmax aggregation
    float sc;
    {
        float x = *scalep;
        sc = (x > 20.f) ? x : log1pf(expf(x));
    }
    float m = -INFINITY;
    for (int s = tid; s < K_; s += SELT) m = fmaxf(m, sc * sscore[s]);
    red[tid] = m;
    __syncthreads();
    for (int o = SELT / 2; o; o >>= 1) {
        if (tid < o) red[tid] = fmaxf(red[tid], red[tid + o]);
        __syncthreads();
    }
    m = red[0];
    __syncthreads();

    float num = 0.f, den = 0.f;
    for (int s = tid; s < K_; s += SELT) {
        float sv = sscore[s];
        float e = expf(sc * sv - m);
        num = fmaf(e, sv, num);
        den += e;
    }
    red[tid] = num;
    __syncthreads();
    for (int o = SELT / 2; o; o >>= 1) {
        if (tid < o) red[tid] += red[tid + o];
        __syncthreads();
    }
    num = red[0];
    __syncthreads();
    red[tid] = den;
    __syncthreads();
    for (int o = SELT / 2; o; o >>= 1) {
        if (tid < o) red[tid] += red[tid + o];
        __syncthreads();
    }
    den = red[0];

    if (tid == 0) out[row] = num / den;
}

// ---------------------------------------------------------------------------
extern "C" void kernel_launch(void* const* d_in, const int* in_sizes, int n_in,
                              void* d_out, int out_size) {
    const float* fea0  = (const float*)d_in[0];
    const float* neg   = (const float*)d_in[1];
    const float* W     = (const float*)d_in[2];
    const float* bias  = (const float*)d_in[3];
    const float* scale = (const float*)d_in[4];
    float* out = (float*)d_out;

    cudaFuncSetAttribute(gemm_kernel<0>,
                         cudaFuncAttributeMaxDynamicSharedMemorySize, SMEM_TC_BYTES);
    cudaFuncSetAttribute(gemm_kernel<1>,
                         cudaFuncAttributeMaxDynamicSharedMemorySize, SMEM_TC_BYTES);
    cudaFuncSetAttribute(select_kernel,
                         cudaFuncAttributeMaxDynamicSharedMemorySize, SEL_SMEM);

    // 1) sample GEMM: first 2048 columns (hi*hi approx)
    gemm_kernel<0><<<dim3(SAMPN / TNB, B_), 256, SMEM_TC_BYTES>>>(fea0, neg);
    // 2) per-row margin threshold + zero counters
    thresh_kernel<<<B_ * P_, 256>>>();
    // 3) full GEMM with margin filter + index append
    gemm_kernel<1><<<dim3((N_ + TNB - 1) / TNB, B_), 256, SMEM_TC_BYTES>>>(fea0, neg);
    // 4) exact rescore + top-512 + softmax
    select_kernel<<<B_ * P_, SELT, SEL_SMEM>>>(fea0, neg, W, bias, scale, out);
}

// round 8
// speedup vs baseline: 2.0646x; 1.1016x over previous
#include <cuda_runtime.h>
#include <cuda_bf16.h>
#include <math.h>
#include <stdint.h>

#define B_ 8
#define P_ 100
#define N_ 50000
#define D_ 128
#define K_ 512
#define CAP 3072
#define SAMPN 2048
#define BUFW 256
#define SELT 512
#define MARGIN 0.25f
#define THRANK 48

// Scratch (static device globals — no runtime allocation)
__device__ float g_fastsim[(size_t)B_ * P_ * N_];      // fallback-only
__device__ float g_sample[(size_t)B_ * P_ * SAMPN];    // 6.4 MB (hi*hi approx)
__device__ float g_lof[B_ * P_];                       // float thresholds
__device__ int g_cnt[B_ * P_];
__device__ int g_cand[(size_t)B_ * P_ * CAP];          // candidate indices

__device__ __forceinline__ unsigned fkey(float f) {
    unsigned u = __float_as_uint(f);
    return (u & 0x80000000u) ? ~u : (u | 0x80000000u);   // monotonic increasing
}
__device__ __forceinline__ float inv_fkey(unsigned k) {
    return (k & 0x80000000u) ? __uint_as_float(k ^ 0x80000000u)
                             : __uint_as_float(~k);
}

// ---------------------------------------------------------------------------
// GEMM (hi*hi approx): pos @ neg^T tile on mma.sync bf16.
// CTA: 128(m) x 128(n), K=128. 8 warps, 64x32 each. 2 smem tiles (70 KB).
// MODE 0: dense store to g_sample. MODE 1: margin filter + index append.
// ---------------------------------------------------------------------------
#define TNB 128
#define TSTR 136
#define TILE_BYTES (128 * TSTR * 2)
#define SMEM_TC_BYTES (2 * TILE_BYTES)

__device__ __forceinline__ uint32_t smem_u32(const void* p) {
    return (uint32_t)__cvta_generic_to_shared(p);
}
__device__ __forceinline__ void ldm_x4(uint32_t& r0, uint32_t& r1, uint32_t& r2, uint32_t& r3,
                                       uint32_t addr) {
    asm volatile("ldmatrix.sync.aligned.m8n8.x4.shared.b16 {%0,%1,%2,%3}, [%4];"
                 : "=r"(r0), "=r"(r1), "=r"(r2), "=r"(r3) : "r"(addr));
}
__device__ __forceinline__ void ldm_x2(uint32_t& r0, uint32_t& r1, uint32_t addr) {
    asm volatile("ldmatrix.sync.aligned.m8n8.x2.shared.b16 {%0,%1}, [%2];"
                 : "=r"(r0), "=r"(r1) : "r"(addr));
}
__device__ __forceinline__ void mma16816(float& c0, float& c1, float& c2, float& c3,
                                         uint32_t a0, uint32_t a1, uint32_t a2, uint32_t a3,
                                         uint32_t b0, uint32_t b1) {
    asm volatile("mma.sync.aligned.m16n8k16.row.col.f32.bf16.bf16.f32 "
                 "{%0,%1,%2,%3}, {%4,%5,%6,%7}, {%8,%9}, {%0,%1,%2,%3};"
                 : "+f"(c0), "+f"(c1), "+f"(c2), "+f"(c3)
                 : "r"(a0), "r"(a1), "r"(a2), "r"(a3), "r"(b0), "r"(b1));
}

template <int MODE>
__global__ void __launch_bounds__(256) gemm_kernel(const float* __restrict__ pos,
                                                   const float* __restrict__ neg) {
    extern __shared__ __nv_bfloat16 smem[];
    __nv_bfloat16* Ah = smem;
    __nv_bfloat16* Bh = smem + 128 * TSTR;

    int tid = threadIdx.x;
    int lane = tid & 31;
    int wid = tid >> 5;
    int b = blockIdx.y;
    int n0 = blockIdx.x * TNB;

    const float* Ab = pos + (size_t)b * P_ * D_;
    const float* Bb = neg + (size_t)b * N_ * D_;

    // ---- load + convert (hi only); pad rows / pad n -> zero
#pragma unroll
    for (int i = 0; i < 16; ++i) {
        int f = i * 256 + tid;
        int r = f >> 5;
        int c = (f & 31) << 2;

        float4 va = make_float4(0.f, 0.f, 0.f, 0.f);
        if (r < P_) va = *(const float4*)(Ab + (size_t)r * D_ + c);
        __nv_bfloat162 a0 = __float22bfloat162_rn(make_float2(va.x, va.y));
        __nv_bfloat162 a1 = __float22bfloat162_rn(make_float2(va.z, va.w));
        *(uint2*)(Ah + r * TSTR + c) = make_uint2(*(uint32_t*)&a0, *(uint32_t*)&a1);

        int n = n0 + r;
        float4 vb = make_float4(0.f, 0.f, 0.f, 0.f);
        if (n < N_) vb = *(const float4*)(Bb + (size_t)n * D_ + c);
        __nv_bfloat162 b0 = __float22bfloat162_rn(make_float2(vb.x, vb.y));
        __nv_bfloat162 b1 = __float22bfloat162_rn(make_float2(vb.z, vb.w));
        *(uint2*)(Bh + r * TSTR + c) = make_uint2(*(uint32_t*)&b0, *(uint32_t*)&b1);
    }
    __syncthreads();

    int wm = wid >> 2;
    int wn = wid & 3;
    int mbase = wm * 64;
    int nbase = wn * 32;

    float c[4][4][4];
#pragma unroll
    for (int i = 0; i < 4; ++i)
#pragma unroll
        for (int j = 0; j < 4; ++j)
#pragma unroll
            for (int q = 0; q < 4; ++q) c[i][j][q] = 0.f;

    {
        uint32_t abase = smem_u32(Ah);
        uint32_t bbase = smem_u32(Bh);
        uint32_t aoff = abase + (uint32_t)(lane & 15) * (TSTR * 2) + (uint32_t)(lane >> 4) * 16;
        uint32_t boff = bbase + (uint32_t)(lane & 7) * (TSTR * 2) + (uint32_t)((lane >> 3) & 1) * 16;

#pragma unroll
        for (int kc = 0; kc < 8; ++kc) {
            uint32_t kb = kc * 32;
            uint32_t a0[4], a1[4], a2[4], a3[4];
#pragma unroll
            for (int i = 0; i < 4; ++i)
                ldm_x4(a0[i], a1[i], a2[i], a3[i],
                       aoff + (uint32_t)(mbase + i * 16) * (TSTR * 2) + kb);
            uint32_t b0[4], b1[4];
#pragma unroll
            for (int j = 0; j < 4; ++j)
                ldm_x2(b0[j], b1[j],
                       boff + (uint32_t)(nbase + j * 8) * (TSTR * 2) + kb);
#pragma unroll
            for (int i = 0; i < 4; ++i)
#pragma unroll
                for (int j = 0; j < 4; ++j)
                    mma16816(c[i][j][0], c[i][j][1], c[i][j][2], c[i][j][3],
                             a0[i], a1[i], a2[i], a3[i], b0[j], b1[j]);
        }
    }

    // ---- epilogue
    int mrow0 = mbase + (lane >> 2);
    int ncol0 = n0 + nbase + (lane & 3) * 2;

    if (MODE == 0) {
#pragma unroll
        for (int i = 0; i < 4; ++i) {
            int m0 = mrow0 + i * 16;
            int m1 = m0 + 8;
#pragma unroll
            for (int j = 0; j < 4; ++j) {
                int nc = ncol0 + j * 8;
                if (m0 < P_)
                    *(float2*)(g_sample + (size_t)(b * P_ + m0) * SAMPN + nc) =
                        make_float2(c[i][j][0], c[i][j][1]);
                if (m1 < P_)
                    *(float2*)(g_sample + (size_t)(b * P_ + m1) * SAMPN + nc) =
                        make_float2(c[i][j][2], c[i][j][3]);
            }
        }
    } else {
        __syncthreads();   // tiles dead; reuse smem
        float*    lof    = (float*)smem;            // [128]
        uint32_t* s_wcnt = (uint32_t*)(lof + 128);  // [8]
        uint32_t* s_hist = s_wcnt + 8;              // [128]
        uint32_t* s_base = s_hist + 128;            // [128]
        uint32_t* s_ovf  = s_base + 128;            // [1]
        uint32_t* bufs   = s_ovf + 1;               // [8][BUFW]

        if (tid < 128) {
            lof[tid] = (tid < P_) ? g_lof[b * P_ + tid] : 3.4e38f;
            s_hist[tid] = 0;
        }
        if (tid == 0) *s_ovf = 0;
        __syncthreads();

        // per-warp atomic-free compaction
        unsigned wcnt = 0;
        uint32_t* mybuf = bufs + wid * BUFW;
        unsigned lmask = (1u << lane) - 1u;
#pragma unroll
        for (int i = 0; i < 4; ++i) {
#pragma unroll
            for (int j = 0; j < 4; ++j) {
#pragma unroll
                for (int q = 0; q < 4; ++q) {
                    int m = mrow0 + i * 16 + (q >> 1) * 8;
                    int n = ncol0 + j * 8 + (q & 1);
                    bool pred = (m < P_) && (n < N_) && (c[i][j][q] >= lof[m & 127]);
                    unsigned msk = __ballot_sync(0xffffffffu, pred);
                    if (pred) {
                        unsigned pos = wcnt + __popc(msk & lmask);
                        if (pos < BUFW) mybuf[pos] = ((unsigned)m << 16) | (unsigned)n;
                    }
                    wcnt += __popc(msk);
                }
            }
        }
        if (lane == 0) {
            s_wcnt[wid] = wcnt > BUFW ? BUFW : wcnt;
            if (wcnt > BUFW) *s_ovf = 1;
        }
        __syncthreads();

        // per-row histogram over all warp segments
#pragma unroll
        for (int w = 0; w < 8; ++w) {
            unsigned cw = s_wcnt[w];
            for (unsigned i = tid; i < cw; i += 256)
                atomicAdd(&s_hist[bufs[w * BUFW + i] >> 16], 1u);
        }
        __syncthreads();

        // reserve g_cand space: ONE global atomic per row
        unsigned ovf = *s_ovf;
        if (tid < P_) {
            unsigned add = s_hist[tid] + (ovf ? (CAP + 1) : 0);
            s_base[tid] = add ? (unsigned)atomicAdd(&g_cnt[b * P_ + tid], (int)add) : 0u;
            s_hist[tid] = 0;
        }
        __syncthreads();

        // scatter indices
#pragma unroll
        for (int w = 0; w < 8; ++w) {
            unsigned cw = s_wcnt[w];
            for (unsigned i = tid; i < cw; i += 256) {
                unsigned e = bufs[w * BUFW + i];
                unsigned m = e >> 16;
                unsigned off = atomicAdd(&s_hist[m], 1u);
                unsigned pos = s_base[m] + off;
                if (pos < CAP)
                    g_cand[(size_t)(b * P_ + m) * CAP + pos] = (int)(e & 0xFFFFu);
            }
        }
    }
}

// ---------------------------------------------------------------------------
// shared radix helper
// ---------------------------------------------------------------------------
__device__ void scan_bins(unsigned* hist, unsigned* csum, int nbins, int kr,
                          int sh, unsigned prefix,
                          unsigned* s_thresh, int* s_kr, int tid) {
    int chunks = nbins >> 3;
    if (tid < chunks) {
        unsigned s = 0;
#pragma unroll
        for (int i = 0; i < 8; ++i) s += hist[tid * 8 + i];
        csum[tid] = s;
    }
    __syncthreads();
    if (tid == 0) {
        unsigned cum = 0;
        int c = chunks - 1;
        for (; c > 0; --c) {
            if (cum + csum[c] >= (unsigned)kr) break;
            cum += csum[c];
        }
        int bin = c * 8 + 7;
        for (; bin > c * 8; --bin) {
            if (cum + hist[bin] >= (unsigned)kr) break;
            cum += hist[bin];
        }
        *s_thresh = prefix | ((unsigned)bin << sh);
        *s_kr = kr - (int)cum;
    }
    __syncthreads();
}

// ---------------------------------------------------------------------------
// Threshold kernel: g_lof[row] = (THRANK-th largest of sample) - MARGIN.
// ---------------------------------------------------------------------------
__global__ void __launch_bounds__(256) thresh_kernel() {
    int row = blockIdx.x;
    int tid = threadIdx.x;
    const float* sim = g_sample + (size_t)row * SAMPN;

    __shared__ unsigned hist[2048];
    __shared__ unsigned csum[256];
    __shared__ unsigned s_thresh;
    __shared__ int s_kr;

    unsigned skey[8];
#pragma unroll
    for (int q = 0; q < 2; ++q) {
        float4 v = *(const float4*)(sim + tid * 8 + q * 4);
        skey[q * 4 + 0] = fkey(v.x); skey[q * 4 + 1] = fkey(v.y);
        skey[q * 4 + 2] = fkey(v.z); skey[q * 4 + 3] = fkey(v.w);
    }
    const int      shifts[3] = {21, 10, 0};
    const unsigned masks[3]  = {0x7FFu, 0x7FFu, 0x3FFu};
    const int      nbinsv[3] = {2048, 2048, 1024};
    unsigned prefix = 0, pmask = 0;
    int kr = THRANK;
    for (int pass = 0; pass < 3; ++pass) {
        int sh = shifts[pass]; unsigned mk = masks[pass];
#pragma unroll
        for (int i = 0; i < 8; ++i) hist[tid * 8 + i] = 0;
        __syncthreads();
#pragma unroll
        for (int i = 0; i < 8; ++i) {
            unsigned u = skey[i];
            if ((u & pmask) == prefix) atomicAdd(&hist[(u >> sh) & mk], 1u);
        }
        __syncthreads();
        scan_bins(hist, csum, nbinsv[pass], kr, sh, prefix, &s_thresh, &s_kr, tid);
        prefix = s_thresh; kr = s_kr; pmask |= mk << sh;
        __syncthreads();
    }
    if (tid == 0) {
        g_lof[row] = inv_fkey(prefix) - MARGIN;
        g_cnt[row] = 0;
    }
}

// ---------------------------------------------------------------------------
// Select (512 thr): exact fp32 fast+bilinear dots on candidates -> top-512 ->
// softmax aggregation. Gather: 2 candidates/warp, 16 lanes each.
// ---------------------------------------------------------------------------
#define SEL_SMEM ((2048 + 256 + 3 * CAP + 2 * K_ + 2 * 128 + SELT) * 4)

__global__ void __launch_bounds__(SELT) select_kernel(const float* __restrict__ pos,
                                                      const float* __restrict__ neg,
                                                      const float* __restrict__ Wm,
                                                      const float* __restrict__ biasp,
                                                      const float* __restrict__ scalep,
                                                      float* __restrict__ out) {
    int row = blockIdx.x;
    int b = row / P_;
    int tid = threadIdx.x;

    extern __shared__ unsigned dsm[];
    unsigned* hist  = dsm;                  // 2048
    unsigned* csum  = hist + 2048;          // 256
    int*      candn = (int*)(csum + 256);   // CAP
    unsigned* candk = (unsigned*)(candn + CAP); // CAP
    float*    candb = (float*)(candk + CAP);    // CAP
    int*      sel   = (int*)(candb + CAP);  // K_
    int*      ties  = sel + K_;             // K_
    float*    ppos  = (float*)(ties + K_);  // 128
    float*    spw   = ppos + 128;           // 128
    float*    red   = spw + 128;            // SELT

    __shared__ unsigned s_thresh;
    __shared__ int s_kr, s_cntgt, s_cnteq;
    __shared__ float sscore[K_];

    if (tid < D_) ppos[tid] = pos[(size_t)row * D_ + tid];
    __syncthreads();
    if (tid < D_) {
        float acc = 0.f;
#pragma unroll 8
        for (int d = 0; d < D_; ++d)
            acc = fmaf(ppos[d], Wm[d * D_ + tid], acc);
        spw[tid] = acc;
    }

    int cnt = g_cnt[row];
    bool fb = (cnt < K_) || (cnt > CAP);

    int lane = tid & 31, wid = tid >> 5;

    if (!fb) {
        for (int i = tid; i < cnt; i += SELT)
            candn[i] = g_cand[(size_t)row * CAP + i];
        __syncthreads();

        // exact fp32 dual dots: 2 candidates per warp, 16 lanes each
        int sl = lane & 15;
        int half = lane >> 4;
        float4 p0 = ((const float4*)ppos)[sl];
        float4 p1 = ((const float4*)ppos)[sl + 16];
        float4 w0 = ((const float4*)spw)[sl];
        float4 w1 = ((const float4*)spw)[sl + 16];

        for (int cd0 = wid * 2; cd0 < cnt; cd0 += 2 * (SELT / 32)) {
            int cd = cd0 + half;
            bool valid = (cd < cnt);
            float sf = 0.f, sb = 0.f;
            if (valid) {
                int idx = candn[cd];
                const float4* vr = (const float4*)(neg + ((size_t)b * N_ + idx) * D_);
                float4 v0 = vr[sl];
                float4 v1 = vr[sl + 16];
                sf = v0.x * p0.x + v0.y * p0.y + v0.z * p0.z + v0.w * p0.w
                   + v1.x * p1.x + v1.y * p1.y + v1.z * p1.z + v1.w * p1.w;
                sb = v0.x * w0.x + v0.y * w0.y + v0.z * w0.z + v0.w * w0.w
                   + v1.x * w1.x + v1.y * w1.y + v1.z * w1.z + v1.w * w1.w;
            }
#pragma unroll
            for (int o = 1; o < 16; o <<= 1) {
                sf += __shfl_xor_sync(0xffffffffu, sf, o);
                sb += __shfl_xor_sync(0xffffffffu, sb, o);
            }
            if (valid && sl == 0) {
                candk[cd] = fkey(sf);
                candb[cd] = sb;
            }
        }
    } else {
        __syncthreads();   // ppos ready
        float* simw = g_fastsim + (size_t)row * N_;
        for (int n = tid; n < N_; n += SELT) {
            const float* v = neg + ((size_t)b * N_ + n) * D_;
            float s = 0.f;
#pragma unroll 8
            for (int d = 0; d < D_; ++d) s = fmaf(ppos[d], v[d], s);
            simw[n] = s;
        }
    }
    __syncthreads();

    const int      shifts[3] = {21, 10, 0};
    const unsigned masks[3]  = {0x7FFu, 0x7FFu, 0x3FFu};
    const int      nbinsv[3] = {2048, 2048, 1024};

    // ---- exact 512th-largest fast key -> uth
    unsigned prefix = 0, pmask = 0;
    int kr = K_;
    const float* simr = g_fastsim + (size_t)row * N_;
    for (int pass = 0; pass < 3; ++pass) {
        int sh = shifts[pass]; unsigned mk = masks[pass];
        for (int i = tid; i < 2048; i += SELT) hist[i] = 0;
        __syncthreads();
        if (!fb) {
            for (int i = tid; i < cnt; i += SELT) {
                unsigned u = candk[i];
                if ((u & pmask) == prefix) atomicAdd(&hist[(u >> sh) & mk], 1u);
            }
        } else {
            for (int n = tid; n < N_; n += SELT) {
                unsigned u = fkey(simr[n]);
                if ((u & pmask) == prefix) atomicAdd(&hist[(u >> sh) & mk], 1u);
            }
        }
        __syncthreads();
        scan_bins(hist, csum, nbinsv[pass], kr, sh, prefix, &s_thresh, &s_kr, tid);
        prefix = s_thresh; kr = s_kr; pmask |= mk << sh;
        __syncthreads();
    }
    unsigned uth = prefix;

    // ---- collect winners (> uth) and ties (== uth)
    if (tid == 0) { s_cntgt = 0; s_cnteq = 0; }
    __syncthreads();
    if (!fb) {
        for (int i = tid; i < cnt; i += SELT) {
            unsigned u = candk[i];
            if (u > uth) {
                int q = atomicAdd(&s_cntgt, 1);
                sel[q] = i;                      // buffer index
            } else if (u == uth) {
                int q = atomicAdd(&s_cnteq, 1);
                if (q < K_) ties[q] = i;
            }
        }
    } else {
        for (int n = tid; n < N_; n += SELT) {
            unsigned u = fkey(simr[n]);
            if (u > uth) {
                int q = atomicAdd(&s_cntgt, 1);
                sel[q] = n;                      // direct n index
            } else if (u == uth) {
                int q = atomicAdd(&s_cnteq, 1);
                if (q < K_) ties[q] = n;
            }
        }
    }
    __syncthreads();
    if (tid == 0) {
        int have = s_cntgt;
        int need = K_ - have;
        int te = min(s_cnteq, K_);
        for (int j = 0; j < need; ++j) {
            int bi = -1; long long bv = 0x7fffffffLL;
            for (int t = 0; t < te; ++t) {
                int v = ties[t];
                if (v < 0) continue;
                long long key = fb ? (long long)v : (long long)candn[v];
                if (key < bv) { bv = key; bi = t; }
            }
            if (bi >= 0) { sel[have + j] = ties[bi]; ties[bi] = -1; }
            else         { sel[have + j] = sel[0]; }
        }
    }
    __syncthreads();

    // ---- scores of the 512 selected
    float biasv = *biasp;
    if (!fb) {
        for (int j = tid; j < K_; j += SELT)
            sscore[j] = candb[sel[j]] + biasv;
    } else {
        float4 w4l = ((const float4*)spw)[lane];
        for (int s = wid; s < K_; s += SELT / 32) {
            int idx = sel[s];
            float4 v = ((const float4*)(neg + ((size_t)b * N_ + idx) * D_))[lane];
            float sum = v.x * w4l.x + v.y * w4l.y + v.z * w4l.z + v.w * w4l.w;
#pragma unroll
            for (int o = 16; o; o >>= 1)
                sum += __shfl_xor_sync(0xffffffffu, sum, o);
            if (lane == 0) sscore[s] = sum + biasv;
        }
    }
    __syncthreads();

    // ---- softmax aggregation
    float sc;
    {
        float x = *scalep;
        sc = (x > 20.f) ? x : log1pf(expf(x));
    }
    float m = -INFINITY;
    for (int s = tid; s < K_; s += SELT) m = fmaxf(m, sc * sscore[s]);
    red[tid] = m;
    __syncthreads();
    for (int o = SELT / 2; o; o >>= 1) {
        if (tid < o) red[tid] = fmaxf(red[tid], red[tid + o]);
        __syncthreads();
    }
    m = red[0];
    __syncthreads();

    float num = 0.f, den = 0.f;
    for (int s = tid; s < K_; s += SELT) {
        float sv = sscore[s];
        float e = expf(sc * sv - m);
        num = fmaf(e, sv, num);
        den += e;
    }
    red[tid] = num;
    __syncthreads();
    for (int o = SELT / 2; o; o >>= 1) {
        if (tid < o) red[tid] += red[tid + o];
        __syncthreads();
    }
    num = red[0];
    __syncthreads();
    red[tid] = den;
    __syncthreads();
    for (int o = SELT / 2; o; o >>= 1) {
        if (tid < o) red[tid] += red[tid + o];
        __syncthreads();
    }
    den = red[0];

    if (tid == 0) out[row] = num / den;
}

// ---------------------------------------------------------------------------
extern "C" void kernel_launch(void* const* d_in, const int* in_sizes, int n_in,
                              void* d_out, int out_size) {
    const float* fea0  = (const float*)d_in[0];
    const float* neg   = (const float*)d_in[1];
    const float* W     = (const float*)d_in[2];
    const float* bias  = (const float*)d_in[3];
    const float* scale = (const float*)d_in[4];
    float* out = (float*)d_out;

    cudaFuncSetAttribute(gemm_kernel<0>,
                         cudaFuncAttributeMaxDynamicSharedMemorySize, SMEM_TC_BYTES);
    cudaFuncSetAttribute(gemm_kernel<1>,
                         cudaFuncAttributeMaxDynamicSharedMemorySize, SMEM_TC_BYTES);
    cudaFuncSetAttribute(select_kernel,
                         cudaFuncAttributeMaxDynamicSharedMemorySize, SEL_SMEM);

    // 1) sample GEMM: first 2048 columns (hi*hi approx)
    gemm_kernel<0><<<dim3(SAMPN / TNB, B_), 256, SMEM_TC_BYTES>>>(fea0, neg);
    // 2) per-row margin threshold + zero counters
    thresh_kernel<<<B_ * P_, 256>>>();
    // 3) full GEMM with margin filter + index append
    gemm_kernel<1><<<dim3((N_ + TNB - 1) / TNB, B_), 256, SMEM_TC_BYTES>>>(fea0, neg);
    // 4) exact rescore + top-512 + softmax
    select_kernel<<<B_ * P_, SELT, SEL_SMEM>>>(fea0, neg, W, bias, scale, out);
}

// round 10
// speedup vs baseline: 2.1639x; 1.0481x over previous
#include <cuda_runtime.h>
#include <cuda_bf16.h>
#include <math.h>
#include <stdint.h>

#define B_ 8
#define P_ 100
#define N_ 50000
#define D_ 128
#define K_ 512
#define CAP 3072
#define SAMPN 2048
#define BUFW 256
#define SELT 512
#define MARGIN 0.25f
#define THRANK 48
#define BAND 0.6f

// Scratch (static device globals — no runtime allocation)
__device__ float g_fastsim[(size_t)B_ * P_ * N_];      // fallback-only
__device__ float g_sample[(size_t)B_ * P_ * SAMPN];    // 6.4 MB (hi*hi approx)
__device__ float g_lof[B_ * P_];                       // float thresholds
__device__ int g_cnt[B_ * P_];
__device__ unsigned long long g_cand[(size_t)B_ * P_ * CAP];  // (key<<32)|n

__device__ __forceinline__ unsigned fkey(float f) {
    unsigned u = __float_as_uint(f);
    return (u & 0x80000000u) ? ~u : (u | 0x80000000u);   // monotonic increasing
}
__device__ __forceinline__ float inv_fkey(unsigned k) {
    return (k & 0x80000000u) ? __uint_as_float(k ^ 0x80000000u)
                             : __uint_as_float(~k);
}

// ---------------------------------------------------------------------------
// GEMM (hi*hi approx): pos @ neg^T tile on mma.sync bf16.
// CTA: 128(m) x 128(n), K=128. 8 warps, 64x32 each. 2 smem tiles (70 KB).
// MODE 0: dense store to g_sample. MODE 1: margin filter + (key,n) append.
// ---------------------------------------------------------------------------
#define TNB 128
#define TSTR 136
#define TILE_BYTES (128 * TSTR * 2)
#define SMEM_TC_BYTES (2 * TILE_BYTES)

__device__ __forceinline__ uint32_t smem_u32(const void* p) {
    return (uint32_t)__cvta_generic_to_shared(p);
}
__device__ __forceinline__ void ldm_x4(uint32_t& r0, uint32_t& r1, uint32_t& r2, uint32_t& r3,
                                       uint32_t addr) {
    asm volatile("ldmatrix.sync.aligned.m8n8.x4.shared.b16 {%0,%1,%2,%3}, [%4];"
                 : "=r"(r0), "=r"(r1), "=r"(r2), "=r"(r3) : "r"(addr));
}
__device__ __forceinline__ void ldm_x2(uint32_t& r0, uint32_t& r1, uint32_t addr) {
    asm volatile("ldmatrix.sync.aligned.m8n8.x2.shared.b16 {%0,%1}, [%2];"
                 : "=r"(r0), "=r"(r1) : "r"(addr));
}
__device__ __forceinline__ void mma16816(float& c0, float& c1, float& c2, float& c3,
                                         uint32_t a0, uint32_t a1, uint32_t a2, uint32_t a3,
                                         uint32_t b0, uint32_t b1) {
    asm volatile("mma.sync.aligned.m16n8k16.row.col.f32.bf16.bf16.f32 "
                 "{%0,%1,%2,%3}, {%4,%5,%6,%7}, {%8,%9}, {%0,%1,%2,%3};"
                 : "+f"(c0), "+f"(c1), "+f"(c2), "+f"(c3)
                 : "r"(a0), "r"(a1), "r"(a2), "r"(a3), "r"(b0), "r"(b1));
}

template <int MODE>
__global__ void __launch_bounds__(256) gemm_kernel(const float* __restrict__ pos,
                                                   const float* __restrict__ neg) {
    extern __shared__ __nv_bfloat16 smem[];
    __nv_bfloat16* Ah = smem;
    __nv_bfloat16* Bh = smem + 128 * TSTR;

    int tid = threadIdx.x;
    int lane = tid & 31;
    int wid = tid >> 5;
    int b = blockIdx.y;
    int n0 = blockIdx.x * TNB;

    const float* Ab = pos + (size_t)b * P_ * D_;
    const float* Bb = neg + (size_t)b * N_ * D_;

    // ---- load + convert (hi only); pad rows / pad n -> zero
#pragma unroll
    for (int i = 0; i < 16; ++i) {
        int f = i * 256 + tid;
        int r = f >> 5;
        int c = (f & 31) << 2;

        float4 va = make_float4(0.f, 0.f, 0.f, 0.f);
        if (r < P_) va = *(const float4*)(Ab + (size_t)r * D_ + c);
        __nv_bfloat162 a0 = __float22bfloat162_rn(make_float2(va.x, va.y));
        __nv_bfloat162 a1 = __float22bfloat162_rn(make_float2(va.z, va.w));
        *(uint2*)(Ah + r * TSTR + c) = make_uint2(*(uint32_t*)&a0, *(uint32_t*)&a1);

        int n = n0 + r;
        float4 vb = make_float4(0.f, 0.f, 0.f, 0.f);
        if (n < N_) vb = *(const float4*)(Bb + (size_t)n * D_ + c);
        __nv_bfloat162 b0 = __float22bfloat162_rn(make_float2(vb.x, vb.y));
        __nv_bfloat162 b1 = __float22bfloat162_rn(make_float2(vb.z, vb.w));
        *(uint2*)(Bh + r * TSTR + c) = make_uint2(*(uint32_t*)&b0, *(uint32_t*)&b1);
    }
    __syncthreads();

    int wm = wid >> 2;
    int wn = wid & 3;
    int mbase = wm * 64;
    int nbase = wn * 32;

    float c[4][4][4];
#pragma unroll
    for (int i = 0; i < 4; ++i)
#pragma unroll
        for (int j = 0; j < 4; ++j)
#pragma unroll
            for (int q = 0; q < 4; ++q) c[i][j][q] = 0.f;

    {
        uint32_t abase = smem_u32(Ah);
        uint32_t bbase = smem_u32(Bh);
        uint32_t aoff = abase + (uint32_t)(lane & 15) * (TSTR * 2) + (uint32_t)(lane >> 4) * 16;
        uint32_t boff = bbase + (uint32_t)(lane & 7) * (TSTR * 2) + (uint32_t)((lane >> 3) & 1) * 16;

#pragma unroll
        for (int kc = 0; kc < 8; ++kc) {
            uint32_t kb = kc * 32;
            uint32_t a0[4], a1[4], a2[4], a3[4];
#pragma unroll
            for (int i = 0; i < 4; ++i)
                ldm_x4(a0[i], a1[i], a2[i], a3[i],
                       aoff + (uint32_t)(mbase + i * 16) * (TSTR * 2) + kb);
            uint32_t b0[4], b1[4];
#pragma unroll
            for (int j = 0; j < 4; ++j)
                ldm_x2(b0[j], b1[j],
                       boff + (uint32_t)(nbase + j * 8) * (TSTR * 2) + kb);
#pragma unroll
            for (int i = 0; i < 4; ++i)
#pragma unroll
                for (int j = 0; j < 4; ++j)
                    mma16816(c[i][j][0], c[i][j][1], c[i][j][2], c[i][j][3],
                             a0[i], a1[i], a2[i], a3[i], b0[j], b1[j]);
        }
    }

    // ---- epilogue
    int mrow0 = mbase + (lane >> 2);
    int ncol0 = n0 + nbase + (lane & 3) * 2;

    if (MODE == 0) {
#pragma unroll
        for (int i = 0; i < 4; ++i) {
            int m0 = mrow0 + i * 16;
            int m1 = m0 + 8;
#pragma unroll
            for (int j = 0; j < 4; ++j) {
                int nc = ncol0 + j * 8;
                if (m0 < P_)
                    *(float2*)(g_sample + (size_t)(b * P_ + m0) * SAMPN + nc) =
                        make_float2(c[i][j][0], c[i][j][1]);
                if (m1 < P_)
                    *(float2*)(g_sample + (size_t)(b * P_ + m1) * SAMPN + nc) =
                        make_float2(c[i][j][2], c[i][j][3]);
            }
        }
    } else {
        __syncthreads();   // tiles dead; reuse smem
        // Layout (words): lof[128] wcnt[8] hist[128] base[128] ovf[2] -> 394
        // 394 * 4 = 1576 bytes, 8-byte aligned for the uint2 bufs that follow.
        float*    lof    = (float*)smem;            // [128]
        uint32_t* s_wcnt = (uint32_t*)(lof + 128);  // [8]
        uint32_t* s_hist = s_wcnt + 8;              // [128]
        uint32_t* s_base = s_hist + 128;            // [128]
        uint32_t* s_ovf  = s_base + 128;            // [2] (padded for alignment)
        uint2*    bufs   = (uint2*)(s_ovf + 2);     // [8][BUFW], 8B-aligned

        if (tid < 128) {
            lof[tid] = (tid < P_) ? g_lof[b * P_ + tid] : 3.4e38f;
            s_hist[tid] = 0;
        }
        if (tid == 0) *s_ovf = 0;
        __syncthreads();

        // per-warp atomic-free compaction: (key, m|n)
        unsigned wcnt = 0;
        uint2* mybuf = bufs + wid * BUFW;
        unsigned lmask = (1u << lane) - 1u;
#pragma unroll
        for (int i = 0; i < 4; ++i) {
#pragma unroll
            for (int j = 0; j < 4; ++j) {
#pragma unroll
                for (int q = 0; q < 4; ++q) {
                    int m = mrow0 + i * 16 + (q >> 1) * 8;
                    int n = ncol0 + j * 8 + (q & 1);
                    float v = c[i][j][q];
                    bool pred = (m < P_) && (n < N_) && (v >= lof[m & 127]);
                    unsigned msk = __ballot_sync(0xffffffffu, pred);
                    if (pred) {
                        unsigned pos = wcnt + __popc(msk & lmask);
                        if (pos < BUFW)
                            mybuf[pos] = make_uint2(fkey(v), ((unsigned)m << 16) | (unsigned)n);
                    }
                    wcnt += __popc(msk);
                }
            }
        }
        if (lane == 0) {
            s_wcnt[wid] = wcnt > BUFW ? BUFW : wcnt;
            if (wcnt > BUFW) *s_ovf = 1;
        }
        __syncthreads();

        // per-row histogram over all warp segments
#pragma unroll
        for (int w = 0; w < 8; ++w) {
            unsigned cw = s_wcnt[w];
            for (unsigned i = tid; i < cw; i += 256)
                atomicAdd(&s_hist[bufs[w * BUFW + i].y >> 16], 1u);
        }
        __syncthreads();

        // reserve g_cand space: ONE global atomic per row
        unsigned ovf = *s_ovf;
        if (tid < P_) {
            unsigned add = s_hist[tid] + (ovf ? (CAP + 1) : 0);
            s_base[tid] = add ? (unsigned)atomicAdd(&g_cnt[b * P_ + tid], (int)add) : 0u;
            s_hist[tid] = 0;
        }
        __syncthreads();

        // scatter (key<<32 | n)
#pragma unroll
        for (int w = 0; w < 8; ++w) {
            unsigned cw = s_wcnt[w];
            for (unsigned i = tid; i < cw; i += 256) {
                uint2 e = bufs[w * BUFW + i];
                unsigned m = e.y >> 16;
                unsigned off = atomicAdd(&s_hist[m], 1u);
                unsigned pos = s_base[m] + off;
                if (pos < CAP)
                    g_cand[(size_t)(b * P_ + m) * CAP + pos] =
                        ((unsigned long long)e.x << 32) | (e.y & 0xFFFFu);
            }
        }
    }
}

// ---------------------------------------------------------------------------
// shared radix helper
// ---------------------------------------------------------------------------
__device__ void scan_bins(unsigned* hist, unsigned* csum, int nbins, int kr,
                          int sh, unsigned prefix,
                          unsigned* s_thresh, int* s_kr, int tid) {
    int chunks = nbins >> 3;
    if (tid < chunks) {
        unsigned s = 0;
#pragma unroll
        for (int i = 0; i < 8; ++i) s += hist[tid * 8 + i];
        csum[tid] = s;
    }
    __syncthreads();
    if (tid == 0) {
        unsigned cum = 0;
        int c = chunks - 1;
        for (; c > 0; --c) {
            if (cum + csum[c] >= (unsigned)kr) break;
            cum += csum[c];
        }
        int bin = c * 8 + 7;
        for (; bin > c * 8; --bin) {
            if (cum + hist[bin] >= (unsigned)kr) break;
            cum += hist[bin];
        }
        *s_thresh = prefix | ((unsigned)bin << sh);
        *s_kr = kr - (int)cum;
    }
    __syncthreads();
}

__device__ __constant__ int      c_shifts[3] = {21, 10, 0};
__device__ __constant__ unsigned c_masks[3]  = {0x7FFu, 0x7FFu, 0x3FFu};
__device__ __constant__ int      c_nbins[3]  = {2048, 2048, 1024};

// ---------------------------------------------------------------------------
// Threshold kernel: g_lof[row] = (THRANK-th largest of sample) - MARGIN.
// ---------------------------------------------------------------------------
__global__ void __launch_bounds__(256) thresh_kernel() {
    int row = blockIdx.x;
    int tid = threadIdx.x;
    const float* sim = g_sample + (size_t)row * SAMPN;

    __shared__ unsigned hist[2048];
    __shared__ unsigned csum[256];
    __shared__ unsigned s_thresh;
    __shared__ int s_kr;

    unsigned skey[8];
#pragma unroll
    for (int q = 0; q < 2; ++q) {
        float4 v = *(const float4*)(sim + tid * 8 + q * 4);
        skey[q * 4 + 0] = fkey(v.x); skey[q * 4 + 1] = fkey(v.y);
        skey[q * 4 + 2] = fkey(v.z); skey[q * 4 + 3] = fkey(v.w);
    }
    unsigned prefix = 0, pmask = 0;
    int kr = THRANK;
    for (int pass = 0; pass < 3; ++pass) {
        int sh = c_shifts[pass]; unsigned mk = c_masks[pass];
#pragma unroll
        for (int i = 0; i < 8; ++i) hist[tid * 8 + i] = 0;
        __syncthreads();
#pragma unroll
        for (int i = 0; i < 8; ++i) {
            unsigned u = skey[i];
            if ((u & pmask) == prefix) atomicAdd(&hist[(u >> sh) & mk], 1u);
        }
        __syncthreads();
        scan_bins(hist, csum, c_nbins[pass], kr, sh, prefix, &s_thresh, &s_kr, tid);
        prefix = s_thresh; kr = s_kr; pmask |= mk << sh;
        __syncthreads();
    }
    if (tid == 0) {
        g_lof[row] = inv_fkey(prefix) - MARGIN;
        g_cnt[row] = 0;
    }
}

// ---------------------------------------------------------------------------
// Select (512 thr): approx radix -> band filter -> exact fp32 dual dots on
// band -> exact top-512 -> softmax aggregation.
// ---------------------------------------------------------------------------
#define SEL_SMEM ((2048 + 256 + 4 * CAP + 2 * K_ + 2 * 128 + SELT) * 4)

__global__ void __launch_bounds__(SELT) select_kernel(const float* __restrict__ pos,
                                                      const float* __restrict__ neg,
                                                      const float* __restrict__ Wm,
                                                      const float* __restrict__ biasp,
                                                      const float* __restrict__ scalep,
                                                      float* __restrict__ out) {
    int row = blockIdx.x;
    int b = row / P_;
    int tid = threadIdx.x;

    extern __shared__ unsigned dsm[];
    unsigned* hist  = dsm;                  // 2048
    unsigned* csum  = hist + 2048;          // 256
    unsigned* candk = csum + 256;           // CAP  (approx key -> later exact key)
    int*      candn = (int*)(candk + CAP);  // CAP
    int*      bandn = candn + CAP;          // CAP
    float*    bbil  = (float*)(bandn + CAP);// CAP
    int*      sel   = (int*)(bbil + CAP);   // K_
    int*      ties  = sel + K_;             // K_
    float*    ppos  = (float*)(ties + K_);  // 128
    float*    spw   = ppos + 128;           // 128
    float*    red   = spw + 128;            // SELT

    __shared__ unsigned s_thresh;
    __shared__ int s_kr, s_cntgt, s_cnteq, s_bc;
    __shared__ float sscore[K_];

    if (tid < D_) ppos[tid] = pos[(size_t)row * D_ + tid];
    __syncthreads();
    if (tid < D_) {
        float acc = 0.f;
#pragma unroll 8
        for (int d = 0; d < D_; ++d)
            acc = fmaf(ppos[d], Wm[d * D_ + tid], acc);
        spw[tid] = acc;
    }
    if (tid == 0) s_bc = 0;

    int cnt = g_cnt[row];
    bool fb = (cnt < K_) || (cnt > CAP);

    int lane = tid & 31, wid = tid >> 5;
    int bc = 0;

    if (!fb) {
        for (int i = tid; i < cnt; i += SELT) {
            unsigned long long v = g_cand[(size_t)row * CAP + i];
            candk[i] = (unsigned)(v >> 32);
            candn[i] = (int)(v & 0xFFFFFFFFull);
        }
        __syncthreads();

        // ---- approx radix: 512th-largest approx key
        unsigned prefix = 0, pmask = 0;
        int kr = K_;
        for (int pass = 0; pass < 3; ++pass) {
            int sh = c_shifts[pass]; unsigned mk = c_masks[pass];
            for (int i = tid; i < 2048; i += SELT) hist[i] = 0;
            __syncthreads();
            for (int i = tid; i < cnt; i += SELT) {
                unsigned u = candk[i];
                if ((u & pmask) == prefix) atomicAdd(&hist[(u >> sh) & mk], 1u);
            }
            __syncthreads();
            scan_bins(hist, csum, c_nbins[pass], kr, sh, prefix, &s_thresh, &s_kr, tid);
            prefix = s_thresh; kr = s_kr; pmask |= mk << sh;
            __syncthreads();
        }
        unsigned bandk = fkey(inv_fkey(prefix) - BAND);

        // ---- band filter (ballot-aggregated append)
        int iters = (cnt + SELT - 1) / SELT;
        for (int it = 0; it < iters; ++it) {
            int i = it * SELT + tid;
            bool pred = (i < cnt) && (candk[i] >= bandk);
            unsigned msk = __ballot_sync(0xffffffffu, pred);
            if (msk) {
                int leader = __ffs(msk) - 1;
                unsigned base = 0;
                if (lane == leader) base = atomicAdd((unsigned*)&s_bc, __popc(msk));
                base = __shfl_sync(0xffffffffu, base, leader);
                if (pred)
                    bandn[base + __popc(msk & ((1u << lane) - 1u))] = candn[i];
            }
        }
        __syncthreads();
        bc = s_bc;

        // ---- exact fp32 dual dots on band: 2 candidates/warp, 16 lanes each
        int sl = lane & 15;
        int half = lane >> 4;
        float4 p0 = ((const float4*)ppos)[sl];
        float4 p1 = ((const float4*)ppos)[sl + 16];
        float4 w0 = ((const float4*)spw)[sl];
        float4 w1 = ((const float4*)spw)[sl + 16];

        for (int cd0 = wid * 2; cd0 < bc; cd0 += 2 * (SELT / 32)) {
            int cd = cd0 + half;
            bool valid = (cd < bc);
            float sf = 0.f, sb = 0.f;
            if (valid) {
                int idx = bandn[cd];
                const float4* vr = (const float4*)(neg + ((size_t)b * N_ + idx) * D_);
                float4 v0 = vr[sl];
                float4 v1 = vr[sl + 16];
                sf = v0.x * p0.x + v0.y * p0.y + v0.z * p0.z + v0.w * p0.w
                   + v1.x * p1.x + v1.y * p1.y + v1.z * p1.z + v1.w * p1.w;
                sb = v0.x * w0.x + v0.y * w0.y + v0.z * w0.z + v0.w * w0.w
                   + v1.x * w1.x + v1.y * w1.y + v1.z * w1.z + v1.w * w1.w;
            }
#pragma unroll
            for (int o = 1; o < 16; o <<= 1) {
                sf += __shfl_xor_sync(0xffffffffu, sf, o);
                sb += __shfl_xor_sync(0xffffffffu, sb, o);
            }
            if (valid && sl == 0) {
                candk[cd] = fkey(sf);    // candk reused for exact keys
                bbil[cd] = sb;
            }
        }
    } else {
        __syncthreads();   // ppos ready
        float* simw = g_fastsim + (size_t)row * N_;
        for (int n = tid; n < N_; n += SELT) {
            const float* v = neg + ((size_t)b * N_ + n) * D_;
            float s = 0.f;
#pragma unroll 8
            for (int d = 0; d < D_; ++d) s = fmaf(ppos[d], v[d], s);
            simw[n] = s;
        }
    }
    __syncthreads();

    // ---- exact 512th-largest key -> uth
    unsigned prefix = 0, pmask = 0;
    int kr = K_;
    const float* simr = g_fastsim + (size_t)row * N_;
    for (int pass = 0; pass < 3; ++pass) {
        int sh = c_shifts[pass]; unsigned mk = c_masks[pass];
        for (int i = tid; i < 2048; i += SELT) hist[i] = 0;
        __syncthreads();
        if (!fb) {
            for (int i = tid; i < bc; i += SELT) {
                unsigned u = candk[i];
                if ((u & pmask) == prefix) atomicAdd(&hist[(u >> sh) & mk], 1u);
            }
        } else {
            for (int n = tid; n < N_; n += SELT) {
                unsigned u = fkey(simr[n]);
                if ((u & pmask) == prefix) atomicAdd(&hist[(u >> sh) & mk], 1u);
            }
        }
        __syncthreads();
        scan_bins(hist, csum, c_nbins[pass], kr, sh, prefix, &s_thresh, &s_kr, tid);
        prefix = s_thresh; kr = s_kr; pmask |= mk << sh;
        __syncthreads();
    }
    unsigned uth = prefix;

    // ---- collect winners (> uth) and ties (== uth)
    if (tid == 0) { s_cntgt = 0; s_cnteq = 0; }
    __syncthreads();
    if (!fb) {
        for (int i = tid; i < bc; i += SELT) {
            unsigned u = candk[i];
            if (u > uth) {
                int q = atomicAdd(&s_cntgt, 1);
                sel[q] = i;                      // band index
            } else if (u == uth) {
                int q = atomicAdd(&s_cnteq, 1);
                if (q < K_) ties[q] = i;
            }
        }
    } else {
        for (int n = tid; n < N_; n += SELT) {
            unsigned u = fkey(simr[n]);
            if (u > uth) {
                int q = atomicAdd(&s_cntgt, 1);
                sel[q] = n;                      // direct n index
            } else if (u == uth) {
                int q = atomicAdd(&s_cnteq, 1);
                if (q < K_) ties[q] = n;
            }
        }
    }
    __syncthreads();
    if (tid == 0) {
        int have = s_cntgt;
        int need = K_ - have;
        int te = min(s_cnteq, K_);
        for (int j = 0; j < need; ++j) {
            int bi = -1; long long bv = 0x7fffffffLL;
            for (int t = 0; t < te; ++t) {
                int v = ties[t];
                if (v < 0) continue;
                long long key = fb ? (long long)v : (long long)bandn[v];
                if (key < bv) { bv = key; bi = t; }
            }
            if (bi >= 0) { sel[have + j] = ties[bi]; ties[bi] = -1; }
            else         { sel[have + j] = sel[0]; }
        }
    }
    __syncthreads();

    // ---- scores of the 512 selected
    float biasv = *biasp;
    if (!fb) {
        for (int j = tid; j < K_; j += SELT)
            sscore[j] = bbil[sel[j]] + biasv;
    } else {
        float4 w4l = ((const float4*)spw)[lane];
        for (int s = wid; s < K_; s += SELT / 32) {
            int idx = sel[s];
            float4 v = ((const float4*)(neg + ((size_t)b * N_ + idx) * D_))[lane];
            float sum = v.x * w4l.x + v.y * w4l.y + v.z * w4l.z + v.w * w4l.w;
#pragma unroll
            for (int o = 16; o; o >>= 1)
                sum += __shfl_xor_sync(0xffffffffu, sum, o);
            if (lane == 0) sscore[s] = sum + biasv;
        }
    }
    __syncthreads();

    // ---- softmax aggregation
    float sc;
    {
        float x = *scalep;
        sc = (x > 20.f) ? x : log1pf(expf(x));
    }
    float m = -INFINITY;
    for (int s = tid; s < K_; s += SELT) m = fmaxf(m, sc * sscore[s]);
    red[tid] = m;
    __syncthreads();
    for (int o = SELT / 2; o; o >>= 1) {
        if (tid < o) red[tid] = fmaxf(red[tid], red[tid + o]);
        __syncthreads();
    }
    m = red[0];
    __syncthreads();

    float num = 0.f, den = 0.f;
    for (int s = tid; s < K_; s += SELT) {
        float sv = sscore[s];
        float e = expf(sc * sv - m);
        num = fmaf(e, sv, num);
        den += e;
    }
    red[tid] = num;
    __syncthreads();
    for (int o = SELT / 2; o; o >>= 1) {
        if (tid < o) red[tid] += red[tid + o];
        __syncthreads();
    }
    num = red[0];
    __syncthreads();
    red[tid] = den;
    __syncthreads();
    for (int o = SELT / 2; o; o >>= 1) {
        if (tid < o) red[tid] += red[tid + o];
        __syncthreads();
    }
    den = red[0];

    if (tid == 0) out[row] = num / den;
}

// ---------------------------------------------------------------------------
extern "C" void kernel_launch(void* const* d_in, const int* in_sizes, int n_in,
                              void* d_out, int out_size) {
    const float* fea0  = (const float*)d_in[0];
    const float* neg   = (const float*)d_in[1];
    const float* W     = (const float*)d_in[2];
    const float* bias  = (const float*)d_in[3];
    const float* scale = (const float*)d_in[4];
    float* out = (float*)d_out;

    cudaFuncSetAttribute(gemm_kernel<0>,
                         cudaFuncAttributeMaxDynamicSharedMemorySize, SMEM_TC_BYTES);
    cudaFuncSetAttribute(gemm_kernel<1>,
                         cudaFuncAttributeMaxDynamicSharedMemorySize, SMEM_TC_BYTES);
    cudaFuncSetAttribute(select_kernel,
                         cudaFuncAttributeMaxDynamicSharedMemorySize, SEL_SMEM);

    // 1) sample GEMM: first 2048 columns (hi*hi approx)
    gemm_kernel<0><<<dim3(SAMPN / TNB, B_), 256, SMEM_TC_BYTES>>>(fea0, neg);
    // 2) per-row margin threshold + zero counters
    thresh_kernel<<<B_ * P_, 256>>>();
    // 3) full GEMM with margin filter + (key,n) append
    gemm_kernel<1><<<dim3((N_ + TNB - 1) / TNB, B_), 256, SMEM_TC_BYTES>>>(fea0, neg);
    // 4) band-filtered exact rescore + top-512 + softmax
    select_kernel<<<B_ * P_, SELT, SEL_SMEM>>>(fea0, neg, W, bias, scale, out);
}